// round 13
// baseline (speedup 1.0000x reference)
#include <cuda_runtime.h>
#include <math.h>
#include <cstdint>

// ---------------------------------------------------------------------------
// Problem constants
// ---------------------------------------------------------------------------
#define NB   2
#define CMS  8
#define CHS  128
#define HH   512
#define HS   128
#define QS   32
#define KK9  (CHS*9)        // 1152 : conv_k im2col K
#define NPX  (QS*QS)        // 1024
#define SPL  8
#define KSP  (KK9/SPL)      // 144

typedef unsigned long long ull;

// ---------------------------------------------------------------------------
// Scratch
// ---------------------------------------------------------------------------
__device__ float g_v[NB*CMS*HH*HH];            // 16 MB
__device__ float g_q[NB*CMS*NPX];
__device__ float g_k[NB*CHS*NPX];
__device__ float g_k0max[NB];
__device__ float g_weff[NB*CMS*9*CHS];         // [n][k=i*9+tap][co]
__device__ float g_kim[NB*KK9*NPX];
__device__ float g_kpart[SPL*NB*CHS*NPX];

__device__ __forceinline__ float lrelu(float x) { return x >= 0.f ? x : 0.01f * x; }

#define FMA_F32X2(d, a, b, c) \
    asm("fma.rn.f32x2 %0, %1, %2, %3;" : "=l"(d) : "l"(a), "l"(b), "l"(c))
#define PACK2(out, lo, hi) \
    asm("mov.b64 %0, {%1, %2};" : "=l"(out) : "r"(lo), "r"(hi))
#define UNPACK2(lo, hi, in) \
    asm("mov.b64 {%0, %1}, %2;" : "=r"(lo), "=r"(hi) : "l"(in))
#define CVT_TF32(out, in) \
    asm("cvt.rna.tf32.f32 %0, %1;" : "=r"(out) : "f"(in))

// ===========================================================================
// STAGE 1: conv_v + conv_q + im2col_k   (independent input-only kernels)
// ===========================================================================
__shared__ __align__(16) float s1buf[8*34*36 + 8*9*8];   // 41.5 KB (conv_v max)

__device__ void body_conv_v(int b, const float* __restrict__ x,
                            const float* __restrict__ Wv,
                            const float* __restrict__ bv) {
    float* s_in = s1buf;                  // 8*34*36
    float* s_w  = s1buf + 8*34*36;        // 8*9*8
    int bx = (b & 15) * 32, by = ((b >> 4) & 15) * 32, n = b >> 8;
    int tid = threadIdx.x;

    for (int e = tid; e < 8*8*9; e += 256) {
        int co = e / 72, rem = e % 72;
        s_w[rem*8 + co] = Wv[e];
    }
    for (int e = tid; e < 8*34*34; e += 256) {
        int cin = e / 1156, rem = e % 1156, r = rem / 34, c = rem % 34;
        int gh = by - 1 + r, gw = bx - 1 + c;
        float v = 0.f;
        if ((unsigned)gh < (unsigned)HH && (unsigned)gw < (unsigned)HH)
            v = x[((n*CMS + cin)*HH + gh)*HH + gw];
        s_in[(cin*34 + r)*36 + c] = v;
    }
    __syncthreads();

    int lx = tid & 31, ly0 = (tid >> 5) * 4;
    ull accp[4][4];
    #pragma unroll
    for (int j = 0; j < 4; j++) {
        ull bj; PACK2(bj, __float_as_uint(bv[2*j]), __float_as_uint(bv[2*j+1]));
        #pragma unroll
        for (int p = 0; p < 4; p++) accp[j][p] = bj;
    }
    #pragma unroll
    for (int cin = 0; cin < 8; cin++) {
        ull vv[6][3];
        #pragma unroll
        for (int rr = 0; rr < 6; rr++)
            #pragma unroll
            for (int dx = 0; dx < 3; dx++) {
                unsigned u = __float_as_uint(s_in[(cin*34 + ly0 + rr)*36 + lx + dx]);
                PACK2(vv[rr][dx], u, u);
            }
        #pragma unroll
        for (int tap = 0; tap < 9; tap++) {
            int dy = tap / 3, dx = tap - dy*3;
            const ulonglong2* wp = (const ulonglong2*)&s_w[(cin*9 + tap)*8];
            ulonglong2 wa = wp[0], wb = wp[1];
            ull wj[4] = {wa.x, wa.y, wb.x, wb.y};
            #pragma unroll
            for (int p = 0; p < 4; p++)
                #pragma unroll
                for (int j = 0; j < 4; j++)
                    FMA_F32X2(accp[j][p], wj[j], vv[p + dy][dx], accp[j][p]);
        }
    }
    #pragma unroll
    for (int j = 0; j < 4; j++)
        #pragma unroll
        for (int p = 0; p < 4; p++) {
            unsigned lo, hi; UNPACK2(lo, hi, accp[j][p]);
            int row = by + ly0 + p;
            g_v[((n*CMS + 2*j    )*HH + row)*HH + bx + lx] = lrelu(__uint_as_float(lo));
            g_v[((n*CMS + 2*j + 1)*HH + row)*HH + bx + lx] = lrelu(__uint_as_float(hi));
        }
}

__device__ void body_conv_q(int b, const float* __restrict__ msi,
                            const float* __restrict__ Wq,
                            const float* __restrict__ bq) {
    int n = b >> 5, i = (b >> 2) & 7, qy = b & 3;
    int tid = threadIdx.x;
    int ox = tid >> 3, ci = tid & 7;
    float* s_wq = s1buf;

    if (tid < 72) s_wq[tid] = Wq[i*72 + tid];
    __syncthreads();

    float bias = bq[i];
    for (int r = 0; r < 8; r++) {
        int oy = qy*8 + r;
        float acc = 0.f;
        #pragma unroll
        for (int dy = 0; dy < 3; dy++) {
            int row = oy*16 + dy - 1;
            if ((unsigned)row >= (unsigned)HH) continue;
            #pragma unroll
            for (int dx = 0; dx < 3; dx++) {
                int col = ox*16 + dx - 1;
                if ((unsigned)col >= (unsigned)HH) continue;
                acc = fmaf(s_wq[ci*9 + dy*3 + dx],
                           msi[((n*CMS + ci)*HH + row)*HH + col], acc);
            }
        }
        acc += __shfl_xor_sync(0xffffffffu, acc, 1);
        acc += __shfl_xor_sync(0xffffffffu, acc, 2);
        acc += __shfl_xor_sync(0xffffffffu, acc, 4);
        if (ci == 0)
            g_q[((n*CMS + i)*QS + oy)*QS + ox] = lrelu(acc + bias);
    }
}

__device__ void body_im2col(int b, const float* __restrict__ hsi) {
    int k = b % KK9, n = b / KK9;
    int ci = k / 9, tap = k % 9;
    int dy = tap / 3, dx = tap % 3;
    const float* src = hsi + (n*CHS + ci)*HS*HS;
    float* dst = g_kim + (n*KK9 + k)*NPX;
    for (int px = threadIdx.x; px < NPX; px += 256) {
        int oy = px >> 5, ox = px & 31;
        int row = 4*oy + dy - 1, col = 4*ox + dx - 1;
        float v = 0.f;
        if ((unsigned)row < (unsigned)HS && (unsigned)col < (unsigned)HS)
            v = src[row*HS + col];
        dst[px] = v;
    }
}

__global__ void __launch_bounds__(256) stage1_kernel(const float* __restrict__ hrms,
                                                     const float* __restrict__ msi,
                                                     const float* __restrict__ hsi,
                                                     const float* __restrict__ Wv,
                                                     const float* __restrict__ bv,
                                                     const float* __restrict__ Wq,
                                                     const float* __restrict__ bq) {
    int b = blockIdx.x;
    if (b < 512)       body_conv_v(b, hrms, Wv, bv);
    else if (b < 576)  body_conv_q(b - 512, msi, Wq, bq);
    else               body_im2col(b - 576, hsi);
}

// ===========================================================================
// STAGE 2: gemm_k (split-K f32x2) + qnorm
// ===========================================================================
__device__ void body_gemm_k(int b, const float* __restrict__ Wk) {
    __shared__ __align__(16) float s_w[16*68];
    __shared__ __align__(16) float s_im[16*128];
    int px0 = (b & 7) * 128;
    int co0 = ((b >> 3) & 1) * 64;
    int z = b >> 4;
    int n = z >> 3, s = z & 7;
    int k0 = s * KSP;
    int tid = threadIdx.x;
    int c8 = tid >> 5, pxq = tid & 31;

    ull acc[4][4];
    #pragma unroll
    for (int j = 0; j < 4; j++)
        #pragma unroll
        for (int p = 0; p < 4; p++) acc[j][p] = 0ull;

    for (int cc = 0; cc < KSP/16; cc++) {
        int kbase = k0 + cc*16;
        #pragma unroll
        for (int e = tid; e < 1024; e += 256) {
            int co = e >> 4, kk = e & 15;
            s_w[kk*68 + co] = Wk[(co0 + co)*KK9 + kbase + kk];
        }
        #pragma unroll
        for (int e = tid; e < 2048; e += 256) {
            int kk = e >> 7, p = e & 127;
            s_im[kk*128 + p] = g_kim[(n*KK9 + kbase + kk)*NPX + px0 + p];
        }
        __syncthreads();
        #pragma unroll
        for (int kk = 0; kk < 16; kk++) {
            const ulonglong2* wp = (const ulonglong2*)&s_w[kk*68 + c8*8];
            ulonglong2 wa = wp[0], wb = wp[1];
            ull wj[4] = {wa.x, wa.y, wb.x, wb.y};
            float4 im = *(const float4*)&s_im[kk*128 + pxq*4];
            float imv[4] = {im.x, im.y, im.z, im.w};
            #pragma unroll
            for (int p = 0; p < 4; p++) {
                unsigned u = __float_as_uint(imv[p]);
                ull vv; PACK2(vv, u, u);
                #pragma unroll
                for (int j = 0; j < 4; j++)
                    FMA_F32X2(acc[j][p], wj[j], vv, acc[j][p]);
            }
        }
        __syncthreads();
    }

    int pbase = (s*NB + n)*CHS;
    #pragma unroll
    for (int j = 0; j < 4; j++) {
        int co = co0 + c8*8 + 2*j;
        #pragma unroll
        for (int p = 0; p < 4; p++) {
            unsigned lo, hi; UNPACK2(lo, hi, acc[j][p]);
            int px = px0 + pxq*4 + p;
            g_kpart[(pbase + co    )*NPX + px] = __uint_as_float(lo);
            g_kpart[(pbase + co + 1)*NPX + px] = __uint_as_float(hi);
        }
    }
}

__device__ void body_qnorm(int n) {
    int warp = threadIdx.x >> 5, lane = threadIdx.x & 31;
    const float* qp = g_q + (n*CMS + warp)*NPX;
    float s = 0.f;
    for (int j = lane; j < NPX; j += 32) { float v = qp[j]; s += v*v; }
    #pragma unroll
    for (int o = 16; o; o >>= 1) s += __shfl_xor_sync(0xffffffffu, s, o);
    __shared__ float sn[8];
    if (lane == 0) sn[warp] = sqrtf(s);
    __syncthreads();
    if (threadIdx.x == 0) {
        float m = sn[0];
        #pragma unroll
        for (int i = 1; i < 8; i++) m = fmaxf(m, sn[i]);
        g_k0max[n] = m;
    }
}

__global__ void __launch_bounds__(256) stage2_kernel(const float* __restrict__ Wk) {
    int b = blockIdx.x;
    if (b < 256) body_gemm_k(b, Wk);
    else         body_qnorm(b - 256);
}

// ===========================================================================
// STAGE 3: reduce split-K partials + bias + lrelu -> g_k
// ===========================================================================
__global__ void __launch_bounds__(256) reduce_k_kernel(const float* __restrict__ bk) {
    int idx4 = blockIdx.x * 256 + threadIdx.x;
    int idx = idx4 * 4;
    int co = (idx >> 10) & 127;
    float4 sum = make_float4(0.f, 0.f, 0.f, 0.f);
    #pragma unroll
    for (int s = 0; s < SPL; s++) {
        float4 v = ((const float4*)g_kpart)[s*65536 + idx4];
        sum.x += v.x; sum.y += v.y; sum.z += v.z; sum.w += v.w;
    }
    float b = bk[co];
    float4 o;
    o.x = lrelu(sum.x + b); o.y = lrelu(sum.y + b);
    o.z = lrelu(sum.z + b); o.w = lrelu(sum.w + b);
    ((float4*)g_k)[idx4] = o;
}

// ===========================================================================
// STAGE 4: att softmax + weff, fused.  512 threads: (c | co) x 4-way part split
// ===========================================================================
__global__ void __launch_bounds__(512) attweff_kernel(const float* __restrict__ Wr) {
    __shared__ float s_q[NPX];
    __shared__ float s_red[512];
    __shared__ float s_att[128];
    __shared__ float s_sc[2];

    int b = blockIdx.x, n = b >> 3;
    int tid = threadIdx.x;
    int c = tid & 127, part = tid >> 7;

    for (int j = tid; j < NPX; j += 512) s_q[j] = g_q[b*NPX + j];
    __syncthreads();

    // dot <q, k[c]> split 4 ways
    const float4* kp = (const float4*)(g_k + (n*CHS + c)*NPX) + part*64;
    const float4* qp = (const float4*)s_q + part*64;
    float acc = 0.f;
    #pragma unroll 4
    for (int j = 0; j < 64; j++) {
        float4 kv = kp[j], qv = qp[j];
        acc += kv.x*qv.x + kv.y*qv.y + kv.z*qv.z + kv.w*qv.w;
    }
    s_red[part*128 + c] = acc;
    __syncthreads();

    float s = 0.f;
    if (tid < 128) {
        s = (s_red[tid] + s_red[128 + tid] + s_red[256 + tid] + s_red[384 + tid])
            * (10.0f / g_k0max[n]);
        s_red[tid] = s;
    }
    __syncthreads();
    for (int off = 64; off; off >>= 1) {
        if (tid < off) s_red[tid] = fmaxf(s_red[tid], s_red[tid + off]);
        __syncthreads();
    }
    if (tid == 0) s_sc[0] = s_red[0];
    __syncthreads();
    float e = 0.f;
    if (tid < 128) { e = expf(s - s_sc[0]); s_red[tid] = e; }
    __syncthreads();
    for (int off = 64; off; off >>= 1) {
        if (tid < off) s_red[tid] += s_red[tid + off];
        __syncthreads();
    }
    if (tid == 0) s_sc[1] = s_red[0];
    __syncthreads();
    if (tid < 128) s_att[tid] = e / s_sc[1];
    __syncthreads();

    // weff: co = c, sum over bands c2 in part's 32-range
    float acc9[9] = {0,0,0,0,0,0,0,0,0};
    const float* wp = Wr + c*CHS*9;
    int c2base = part * 32;
    for (int c2 = c2base; c2 < c2base + 32; c2++) {
        float a = s_att[c2];
        #pragma unroll
        for (int tap = 0; tap < 9; tap++)
            acc9[tap] = fmaf(wp[c2*9 + tap], a, acc9[tap]);
    }
    #pragma unroll
    for (int tap = 0; tap < 9; tap++) {
        s_red[part*128 + c] = acc9[tap];
        __syncthreads();
        if (tid < 128)
            g_weff[(b*9 + tap)*CHS + tid] =
                (s_red[tid] + s_red[128+tid] + s_red[256+tid] + s_red[384+tid]) * (1.0f/6.0f);
        __syncthreads();
    }
}

// ===========================================================================
// STAGE 5: final conv via mma.sync tf32 — co as M (STG.64 epilogue),
//   A (Weff) fragments register-cached per m-tile-pair, persistent CTAs.
// ===========================================================================
#define HALO_STRIDE 516
#define HALO_FLOATS (8*3*HALO_STRIDE)     // 12384
#define BSTR 136
#define B_FLOATS (72*BSTR)                // 9792
#define FINAL_SMEM ((B_FLOATS + HALO_FLOATS + 128) * 4)   // 89216 B

__global__ void __launch_bounds__(256, 2) final_mma_kernel(const float* __restrict__ br,
                                                           float* __restrict__ out) {
    extern __shared__ float sm[];
    uint32_t* s_B    = (uint32_t*)sm;                 // [k][co] tf32, stride 136
    float*    s_halo = sm + B_FLOATS;                 // 8cin x 3 x 516
    float*    s_br   = sm + B_FLOATS + HALO_FLOATS;   // 128

    int n   = blockIdx.y;
    int tid = threadIdx.x;
    int lane = tid & 31, w = tid >> 5;
    int q = lane & 3, r = lane >> 2;

    // B = Weff (tf32) once per CTA
    const float* wsrc = g_weff + n*72*128;
    for (int e = tid; e < 72*128; e += 256) {
        int k = e >> 7, co = e & 127;
        uint32_t t; CVT_TF32(t, wsrc[k*128 + co]);
        s_B[k*BSTR + co] = t;
    }
    if (tid < 128) s_br[tid] = br[tid];

    // per-lane k -> halo-offset tables (k = kk*8 + q (+4))
    int off0[9], off1[9];
    #pragma unroll
    for (int kk = 0; kk < 9; kk++) {
        int k = kk*8 + q;
        int cin = k / 9, tap = k % 9;
        off0[kk] = (cin*3 + tap/3)*HALO_STRIDE + (tap%3);
        k += 4; cin = k / 9; tap = k % 9;
        off1[kk] = (cin*3 + tap/3)*HALO_STRIDE + (tap%3);
    }

    const size_t plane = (size_t)HH * HH;
    int px_w = w * 64;

    for (int y = blockIdx.x; y < HH; y += gridDim.x) {
        __syncthreads();   // halo region free
        for (int e = tid; e < 8*3*514; e += 256) {
            int cin = e / 1542, rem = e % 1542, rr = rem / 514, cc = rem % 514;
            int gh = y - 1 + rr, gw = cc - 1;
            float v = 0.f;
            if ((unsigned)gh < (unsigned)HH && (unsigned)gw < (unsigned)HH)
                v = g_v[((n*CMS + cin)*HH + gh)*HH + gw];
            s_halo[(cin*3 + rr)*HALO_STRIDE + cc] = v;
        }
        __syncthreads();

        float* orow = out + (size_t)(n*CHS) * plane + (size_t)y * HH;

        #pragma unroll
        for (int mp = 0; mp < 4; mp++) {
            int cb = mp * 32;
            // A fragments for 2 m-tiles x 9 k-steps
            uint32_t a[2][9][4];
            #pragma unroll
            for (int m2 = 0; m2 < 2; m2++) {
                int co0 = cb + m2*16 + r;
                #pragma unroll
                for (int kk = 0; kk < 9; kk++) {
                    const uint32_t* bp = &s_B[(kk*8 + q)*BSTR + co0];
                    a[m2][kk][0] = bp[0];
                    a[m2][kk][1] = bp[8];
                    a[m2][kk][2] = bp[4*BSTR];
                    a[m2][kk][3] = bp[4*BSTR + 8];
                }
            }
            float b00 = s_br[cb + r],      b01 = s_br[cb + r + 8];
            float b10 = s_br[cb + 16 + r], b11 = s_br[cb + 24 + r];

            #pragma unroll
            for (int j = 0; j < 8; j++) {
                int px0 = px_w + j*8;
                float d00 = b00, d01 = b00, d02 = b01, d03 = b01;
                float d10 = b10, d11 = b10, d12 = b11, d13 = b11;
                #pragma unroll
                for (int kk = 0; kk < 9; kk++) {
                    uint32_t bb0, bb1;
                    CVT_TF32(bb0, s_halo[off0[kk] + px0 + r]);
                    CVT_TF32(bb1, s_halo[off1[kk] + px0 + r]);
                    asm("mma.sync.aligned.m16n8k8.row.col.f32.tf32.tf32.f32 "
                        "{%0,%1,%2,%3}, {%4,%5,%6,%7}, {%8,%9}, {%0,%1,%2,%3};"
                        : "+f"(d00), "+f"(d01), "+f"(d02), "+f"(d03)
                        : "r"(a[0][kk][0]), "r"(a[0][kk][1]), "r"(a[0][kk][2]), "r"(a[0][kk][3]),
                          "r"(bb0), "r"(bb1));
                    asm("mma.sync.aligned.m16n8k8.row.col.f32.tf32.tf32.f32 "
                        "{%0,%1,%2,%3}, {%4,%5,%6,%7}, {%8,%9}, {%0,%1,%2,%3};"
                        : "+f"(d10), "+f"(d11), "+f"(d12), "+f"(d13)
                        : "r"(a[1][kk][0]), "r"(a[1][kk][1]), "r"(a[1][kk][2]), "r"(a[1][kk][3]),
                          "r"(bb0), "r"(bb1));
                }
                float* p0 = orow + (size_t)(cb + r     )*plane + px0 + 2*q;
                float* p1 = orow + (size_t)(cb + r + 8 )*plane + px0 + 2*q;
                float* p2 = orow + (size_t)(cb + r + 16)*plane + px0 + 2*q;
                float* p3 = orow + (size_t)(cb + r + 24)*plane + px0 + 2*q;
                *(float2*)p0 = make_float2(lrelu(d00), lrelu(d01));
                *(float2*)p1 = make_float2(lrelu(d02), lrelu(d03));
                *(float2*)p2 = make_float2(lrelu(d10), lrelu(d11));
                *(float2*)p3 = make_float2(lrelu(d12), lrelu(d13));
            }
        }
    }
}

// ---------------------------------------------------------------------------
// Launch
// ---------------------------------------------------------------------------
extern "C" void kernel_launch(void* const* d_in, const int* in_sizes, int n_in,
                              void* d_out, int out_size) {
    (void)in_sizes; (void)n_in; (void)out_size;
    const float* hrms = (const float*)d_in[0];
    const float* msi  = (const float*)d_in[1];
    const float* hsi  = (const float*)d_in[2];
    const float* Wv   = (const float*)d_in[3];
    const float* bv   = (const float*)d_in[4];
    const float* Wq   = (const float*)d_in[5];
    const float* bq   = (const float*)d_in[6];
    const float* Wk   = (const float*)d_in[7];
    const float* bk   = (const float*)d_in[8];
    const float* Wr   = (const float*)d_in[9];
    const float* br   = (const float*)d_in[10];
    float* out = (float*)d_out;

    cudaFuncSetAttribute(final_mma_kernel,
                         cudaFuncAttributeMaxDynamicSharedMemorySize, FINAL_SMEM);

    stage1_kernel<<<576 + NB*KK9, 256>>>(hrms, msi, hsi, Wv, bv, Wq, bq);
    stage2_kernel<<<258, 256>>>(Wk);
    reduce_k_kernel<<<256, 256>>>(bk);
    attweff_kernel<<<NB*CMS, 512>>>(Wr);
    final_mma_kernel<<<dim3(148, NB), 256, FINAL_SMEM>>>(br, out);
}

// round 14
// speedup vs baseline: 1.7492x; 1.7492x over previous
#include <cuda_runtime.h>
#include <math.h>
#include <cstdint>

// ---------------------------------------------------------------------------
// Problem constants
// ---------------------------------------------------------------------------
#define NB   2
#define CMS  8
#define CHS  128
#define HH   512
#define HS   128
#define QS   32
#define KK9  (CHS*9)        // 1152 : conv_k im2col K
#define NPX  (QS*QS)        // 1024
#define SPL  8
#define KSP  (KK9/SPL)      // 144

typedef unsigned long long ull;

// ---------------------------------------------------------------------------
// Scratch
// ---------------------------------------------------------------------------
__device__ float g_v[NB*CMS*HH*HH];            // 16 MB
__device__ float g_q[NB*CMS*NPX];
__device__ float g_k[NB*CHS*NPX];
__device__ float g_k0max[NB];
__device__ float g_att[NB*CMS*CHS];
__device__ float g_weff[NB*CMS*9*CHS];         // [n][k=i*9+tap][co]
__device__ float g_kim[NB*KK9*NPX];
__device__ float g_kpart[SPL*NB*CHS*NPX];
__device__ float g_wrt[9*CHS*CHS];             // WrT[tap][c][co]

__device__ __forceinline__ float lrelu(float x) { return x >= 0.f ? x : 0.01f * x; }

#define FMA_F32X2(d, a, b, c) \
    asm("fma.rn.f32x2 %0, %1, %2, %3;" : "=l"(d) : "l"(a), "l"(b), "l"(c))
#define PACK2(out, lo, hi) \
    asm("mov.b64 %0, {%1, %2};" : "=l"(out) : "r"(lo), "r"(hi))
#define UNPACK2(lo, hi, in) \
    asm("mov.b64 {%0, %1}, %2;" : "=r"(lo), "=r"(hi) : "l"(in))
#define CVT_TF32(out, in) \
    asm("cvt.rna.tf32.f32 %0, %1;" : "=r"(out) : "f"(in))

// ---------------------------------------------------------------------------
// K1: conv_v  (8 -> 8, 3x3, stride 1, pad 1) + lrelu      -> g_v
// ---------------------------------------------------------------------------
__global__ void __launch_bounds__(256) conv_v_kernel(const float* __restrict__ x,
                                                     const float* __restrict__ Wv,
                                                     const float* __restrict__ bv) {
    __shared__ float s_in[8*34*36];
    __shared__ float s_w[8*9*8];
    int n  = blockIdx.z;
    int by = blockIdx.y * 32, bx = blockIdx.x * 32;
    int tid = threadIdx.x;

    for (int e = tid; e < 8*8*9; e += 256) {
        int co = e / 72, rem = e % 72;
        s_w[rem*8 + co] = Wv[e];
    }
    for (int e = tid; e < 8*34*34; e += 256) {
        int cin = e / 1156, rem = e % 1156, r = rem / 34, c = rem % 34;
        int gh = by - 1 + r, gw = bx - 1 + c;
        float v = 0.f;
        if ((unsigned)gh < (unsigned)HH && (unsigned)gw < (unsigned)HH)
            v = x[((n*CMS + cin)*HH + gh)*HH + gw];
        s_in[(cin*34 + r)*36 + c] = v;
    }
    __syncthreads();

    int lx = tid & 31, ly0 = (tid >> 5) * 4;
    float acc[8][4];
    #pragma unroll
    for (int co = 0; co < 8; co++) {
        float b = bv[co];
        #pragma unroll
        for (int p = 0; p < 4; p++) acc[co][p] = b;
    }
    #pragma unroll
    for (int cin = 0; cin < 8; cin++) {
        float vr[6][3];
        #pragma unroll
        for (int rr = 0; rr < 6; rr++)
            #pragma unroll
            for (int dx = 0; dx < 3; dx++)
                vr[rr][dx] = s_in[(cin*34 + ly0 + rr)*36 + lx + dx];
        #pragma unroll
        for (int tap = 0; tap < 9; tap++) {
            int dy = tap / 3, dx = tap % 3;
            const float* wp = &s_w[(cin*9 + tap)*8];
            #pragma unroll
            for (int co = 0; co < 8; co++) {
                float w = wp[co];
                #pragma unroll
                for (int p = 0; p < 4; p++)
                    acc[co][p] = fmaf(w, vr[p + dy][dx], acc[co][p]);
            }
        }
    }
    #pragma unroll
    for (int co = 0; co < 8; co++)
        #pragma unroll
        for (int p = 0; p < 4; p++)
            g_v[((n*CMS + co)*HH + by + ly0 + p)*HH + bx + lx] = lrelu(acc[co][p]);
}

// ---------------------------------------------------------------------------
// K2: conv_q  (8 -> 8, 3x3, stride 16, pad 1) + lrelu     -> g_q
// ---------------------------------------------------------------------------
__global__ void __launch_bounds__(256) conv_q_kernel(const float* __restrict__ msi,
                                                     const float* __restrict__ Wq,
                                                     const float* __restrict__ bq) {
    int b = blockIdx.x;
    int n = b >> 5, i = (b >> 2) & 7, qy = b & 3;
    int tid = threadIdx.x;
    int ox = tid >> 3, ci = tid & 7;

    __shared__ float s_wq[72];
    if (tid < 72) s_wq[tid] = Wq[i*72 + tid];
    __syncthreads();

    float bias = bq[i];
    for (int r = 0; r < 8; r++) {
        int oy = qy*8 + r;
        float acc = 0.f;
        #pragma unroll
        for (int dy = 0; dy < 3; dy++) {
            int row = oy*16 + dy - 1;
            if ((unsigned)row >= (unsigned)HH) continue;
            #pragma unroll
            for (int dx = 0; dx < 3; dx++) {
                int col = ox*16 + dx - 1;
                if ((unsigned)col >= (unsigned)HH) continue;
                acc = fmaf(s_wq[ci*9 + dy*3 + dx],
                           msi[((n*CMS + ci)*HH + row)*HH + col], acc);
            }
        }
        acc += __shfl_xor_sync(0xffffffffu, acc, 1);
        acc += __shfl_xor_sync(0xffffffffu, acc, 2);
        acc += __shfl_xor_sync(0xffffffffu, acc, 4);
        if (ci == 0)
            g_q[((n*CMS + i)*QS + oy)*QS + ox] = lrelu(acc + bias);
    }
}

// ---------------------------------------------------------------------------
// K3: k0_max
// ---------------------------------------------------------------------------
__global__ void qnorm_kernel() {
    int n = blockIdx.x;
    int warp = threadIdx.x >> 5, lane = threadIdx.x & 31;
    const float* qp = g_q + (n*CMS + warp)*NPX;
    float s = 0.f;
    for (int j = lane; j < NPX; j += 32) { float v = qp[j]; s += v*v; }
    #pragma unroll
    for (int o = 16; o; o >>= 1) s += __shfl_xor_sync(0xffffffffu, s, o);
    __shared__ float sn[8];
    if (lane == 0) sn[warp] = sqrtf(s);
    __syncthreads();
    if (threadIdx.x == 0) {
        float m = sn[0];
        #pragma unroll
        for (int i = 1; i < 8; i++) m = fmaxf(m, sn[i]);
        g_k0max[n] = m;
    }
}

// ---------------------------------------------------------------------------
// K4a: im2col for conv_k
// ---------------------------------------------------------------------------
__global__ void __launch_bounds__(256) im2col_k_kernel(const float* __restrict__ hsi) {
    int k = blockIdx.x;
    int n = blockIdx.y;
    int ci = k / 9, tap = k % 9;
    int dy = tap / 3, dx = tap % 3;
    const float* src = hsi + (n*CHS + ci)*HS*HS;
    float* dst = g_kim + (n*KK9 + k)*NPX;
    for (int px = threadIdx.x; px < NPX; px += 256) {
        int oy = px >> 5, ox = px & 31;
        int row = 4*oy + dy - 1, col = 4*ox + dx - 1;
        float v = 0.f;
        if ((unsigned)row < (unsigned)HS && (unsigned)col < (unsigned)HS)
            v = src[row*HS + col];
        dst[px] = v;
    }
}

// ---------------------------------------------------------------------------
// K4b: split-K GEMM for conv_k (f32x2)
// ---------------------------------------------------------------------------
__global__ void __launch_bounds__(256) gemm_k_kernel(const float* __restrict__ Wk) {
    __shared__ __align__(16) float s_w[16*68];
    __shared__ __align__(16) float s_im[16*128];
    int px0 = blockIdx.x * 128;
    int co0 = blockIdx.y * 64;
    int z = blockIdx.z;
    int n = z >> 3, s = z & 7;
    int k0 = s * KSP;
    int tid = threadIdx.x;
    int c8 = tid >> 5, pxq = tid & 31;

    ull acc[4][4];
    #pragma unroll
    for (int j = 0; j < 4; j++)
        #pragma unroll
        for (int p = 0; p < 4; p++) acc[j][p] = 0ull;

    for (int cc = 0; cc < KSP/16; cc++) {
        int kbase = k0 + cc*16;
        #pragma unroll
        for (int e = tid; e < 1024; e += 256) {
            int co = e >> 4, kk = e & 15;
            s_w[kk*68 + co] = Wk[(co0 + co)*KK9 + kbase + kk];
        }
        #pragma unroll
        for (int e = tid; e < 2048; e += 256) {
            int kk = e >> 7, p = e & 127;
            s_im[kk*128 + p] = g_kim[(n*KK9 + kbase + kk)*NPX + px0 + p];
        }
        __syncthreads();
        #pragma unroll
        for (int kk = 0; kk < 16; kk++) {
            const ulonglong2* wp = (const ulonglong2*)&s_w[kk*68 + c8*8];
            ulonglong2 wa = wp[0], wb = wp[1];
            ull wj[4] = {wa.x, wa.y, wb.x, wb.y};
            float4 im = *(const float4*)&s_im[kk*128 + pxq*4];
            float imv[4] = {im.x, im.y, im.z, im.w};
            #pragma unroll
            for (int p = 0; p < 4; p++) {
                unsigned u = __float_as_uint(imv[p]);
                ull vv; PACK2(vv, u, u);
                #pragma unroll
                for (int j = 0; j < 4; j++)
                    FMA_F32X2(acc[j][p], wj[j], vv, acc[j][p]);
            }
        }
        __syncthreads();
    }

    int pbase = (s*NB + n)*CHS;
    #pragma unroll
    for (int j = 0; j < 4; j++) {
        int co = co0 + c8*8 + 2*j;
        #pragma unroll
        for (int p = 0; p < 4; p++) {
            unsigned lo, hi; UNPACK2(lo, hi, acc[j][p]);
            int px = px0 + pxq*4 + p;
            g_kpart[(pbase + co    )*NPX + px] = __uint_as_float(lo);
            g_kpart[(pbase + co + 1)*NPX + px] = __uint_as_float(hi);
        }
    }
}

// ---------------------------------------------------------------------------
// K4c: reduce split-K partials + bias + lrelu -> g_k
// ---------------------------------------------------------------------------
__global__ void __launch_bounds__(256) reduce_k_kernel(const float* __restrict__ bk) {
    int idx4 = blockIdx.x * 256 + threadIdx.x;
    int idx = idx4 * 4;
    int co = (idx >> 10) & 127;
    float4 sum = make_float4(0.f, 0.f, 0.f, 0.f);
    #pragma unroll
    for (int s = 0; s < SPL; s++) {
        float4 v = ((const float4*)g_kpart)[s*65536 + idx4];
        sum.x += v.x; sum.y += v.y; sum.z += v.z; sum.w += v.w;
    }
    float b = bk[co];
    float4 o;
    o.x = lrelu(sum.x + b); o.y = lrelu(sum.y + b);
    o.z = lrelu(sum.z + b); o.w = lrelu(sum.w + b);
    ((float4*)g_k)[idx4] = o;
}

// ---------------------------------------------------------------------------
// K5a: Wr transpose -> WrT[tap][c][co]  (coalesced reads; one-time, ~590KB)
// ---------------------------------------------------------------------------
__global__ void __launch_bounds__(256) wrt_kernel(const float* __restrict__ Wr) {
    int e = blockIdx.x * 256 + threadIdx.x;          // 147456 elems -> 576 blocks
    if (e >= 9*CHS*CHS) return;
    int co = e / (CHS*9), rem = e % (CHS*9), c = rem / 9, tap = rem % 9;
    g_wrt[(tap*CHS + c)*CHS + co] = Wr[e];
}

// ---------------------------------------------------------------------------
// K5b: att2 — block per b (16 blocks x 1024 threads): 8 lanes per channel c,
//   coalesced float4 dot + shfl reduce, then in-block softmax.
// ---------------------------------------------------------------------------
__global__ void __launch_bounds__(1024) att2_kernel() {
    __shared__ __align__(16) float s_q[NPX];
    __shared__ float s_red[128];
    __shared__ float s_sc[2];

    int b = blockIdx.x, n = b >> 3;
    int tid = threadIdx.x;
    int c = tid >> 3, t8 = tid & 7;

    s_q[tid] = g_q[b*NPX + tid];
    __syncthreads();

    // dot <q, k[c]>: 8 lanes split the 256 float4s; groups of 8 lanes coalesce 128B
    const float4* kp = (const float4*)(g_k + (n*CHS + c)*NPX);
    const float4* qp = (const float4*)s_q;
    float acc = 0.f;
    #pragma unroll 8
    for (int j = 0; j < 32; j++) {
        int i4 = t8 + j*8;
        float4 kv = kp[i4], qv = qp[i4];
        acc += kv.x*qv.x + kv.y*qv.y + kv.z*qv.z + kv.w*qv.w;
    }
    acc += __shfl_xor_sync(0xffffffffu, acc, 1);
    acc += __shfl_xor_sync(0xffffffffu, acc, 2);
    acc += __shfl_xor_sync(0xffffffffu, acc, 4);
    if (t8 == 0) s_red[c] = acc;
    __syncthreads();

    // softmax over 128 channels (threads 0..127 active in tree; all hit barriers)
    float s = 0.f;
    if (tid < 128) { s = s_red[tid] * (10.0f / g_k0max[n]); s_red[tid] = s; }
    __syncthreads();
    for (int off = 64; off; off >>= 1) {
        if (tid < off) s_red[tid] = fmaxf(s_red[tid], s_red[tid + off]);
        __syncthreads();
    }
    if (tid == 0) s_sc[0] = s_red[0];
    __syncthreads();
    float e = 0.f;
    if (tid < 128) { e = expf(s - s_sc[0]); s_red[tid] = e; }
    __syncthreads();
    for (int off = 64; off; off >>= 1) {
        if (tid < off) s_red[tid] += s_red[tid + off];
        __syncthreads();
    }
    if (tid == 0) s_sc[1] = s_red[0];
    __syncthreads();
    if (tid < 128) g_att[b*CHS + tid] = e / s_sc[1];
}

// ---------------------------------------------------------------------------
// K5c: weff2 — block per (b, tap) = 144 blocks x 128 threads (thread = co).
//   WrT reads fully coalesced across co; WrT is L2-resident (590KB, 16x reuse).
// ---------------------------------------------------------------------------
__global__ void __launch_bounds__(128) weff2_kernel() {
    __shared__ float s_att[128];
    int bid = blockIdx.x;
    int b = bid / 9, tap = bid % 9;
    int co = threadIdx.x;
    s_att[co] = g_att[b*CHS + co];
    __syncthreads();
    const float* wp = g_wrt + tap*CHS*CHS + co;
    float acc = 0.f;
    #pragma unroll 8
    for (int c = 0; c < 128; c++)
        acc = fmaf(s_att[c], wp[c*CHS], acc);
    g_weff[(b*9 + tap)*CHS + co] = acc * (1.0f/6.0f);
}

// ---------------------------------------------------------------------------
// K7: final conv via mma.sync tf32 (px-as-M; measured-good 288.8us version)
// ---------------------------------------------------------------------------
#define HALO_STRIDE 516
#define HALO_FLOATS (8*3*HALO_STRIDE)     // 12384
#define BSTR 136
#define B_FLOATS (72*BSTR)                // 9792
#define FINAL_SMEM ((HALO_FLOATS + B_FLOATS + 128) * 4)   // 89216 B

__global__ void __launch_bounds__(256) final_mma_kernel(const float* __restrict__ br,
                                                        float* __restrict__ out) {
    extern __shared__ float sm[];
    float*    s_halo = sm;                                   // 12384 floats
    uint32_t* s_B    = (uint32_t*)(sm + HALO_FLOATS);        // 9792 (tf32)
    float*    s_br   = sm + HALO_FLOATS + B_FLOATS;          // 128

    int y = blockIdx.x;
    int n = blockIdx.y;
    int tid = threadIdx.x;
    int lane = tid & 31, w = tid >> 5;

    // --- B = Weff (tf32) into smem [k][co], stride 136 ---
    const float* wsrc = g_weff + n*72*128;
    for (int e = tid; e < 72*128; e += 256) {
        int k = e >> 7, co = e & 127;
        uint32_t t; CVT_TF32(t, wsrc[k*128 + co]);
        s_B[k*BSTR + co] = t;
    }
    if (tid < 128) s_br[tid] = br[tid];

    // --- halo: 8 cin x 3 rows x 514 cols (col c <-> gw = c-1) ---
    for (int e = tid; e < 8*3*514; e += 256) {
        int cin = e / 1542, rem = e % 1542, r = rem / 514, c = rem % 514;
        int gh = y - 1 + r, gw = c - 1;
        float v = 0.f;
        if ((unsigned)gh < (unsigned)HH && (unsigned)gw < (unsigned)HH)
            v = g_v[((n*CMS + cin)*HH + gh)*HH + gw];
        s_halo[(cin*3 + r)*HALO_STRIDE + c] = v;
    }
    __syncthreads();

    // --- per-lane k -> halo-offset tables (k = cin*9 + dy*3 + dx) ---
    int off0[9], off1[9];
    #pragma unroll
    for (int kk = 0; kk < 9; kk++) {
        int k = kk*8 + (lane & 3);
        int cin = k / 9, tap = k % 9;
        off0[kk] = (cin*3 + tap/3)*HALO_STRIDE + (tap%3);
        k += 4; cin = k / 9; tap = k % 9;
        off1[kk] = (cin*3 + tap/3)*HALO_STRIDE + (tap%3);
    }

    float* orow = out + (size_t)(n*CHS) * (HH*HH) + (size_t)y * HH;
    const size_t plane = (size_t)HH * HH;

    for (int i = 0; i < 4; i++) {
        int x0 = (w + 8*i) * 16;
        int x  = x0 + (lane >> 2);

        uint32_t a[9][4];
        #pragma unroll
        for (int kk = 0; kk < 9; kk++) {
            float f0 = s_halo[off0[kk] + x];
            float f1 = s_halo[off0[kk] + x + 8];
            float f2 = s_halo[off1[kk] + x];
            float f3 = s_halo[off1[kk] + x + 8];
            CVT_TF32(a[kk][0], f0);
            CVT_TF32(a[kk][1], f1);
            CVT_TF32(a[kk][2], f2);
            CVT_TF32(a[kk][3], f3);
        }

        #pragma unroll 4
        for (int nt = 0; nt < 16; nt++) {
            int n0  = nt * 8;
            int co0 = n0 + 2*(lane & 3);
            float d0 = s_br[co0], d1 = s_br[co0 + 1];
            float d2 = d0,        d3 = d1;
            const uint32_t* bp = &s_B[(lane & 3)*BSTR + n0 + (lane >> 2)];
            #pragma unroll
            for (int kk = 0; kk < 9; kk++) {
                uint32_t b0 = bp[(kk*8    )*BSTR];
                uint32_t b1 = bp[(kk*8 + 4)*BSTR];
                asm("mma.sync.aligned.m16n8k8.row.col.f32.tf32.tf32.f32 "
                    "{%0,%1,%2,%3}, {%4,%5,%6,%7}, {%8,%9}, {%0,%1,%2,%3};"
                    : "+f"(d0), "+f"(d1), "+f"(d2), "+f"(d3)
                    : "r"(a[kk][0]), "r"(a[kk][1]), "r"(a[kk][2]), "r"(a[kk][3]),
                      "r"(b0), "r"(b1));
            }
            orow[(size_t)co0      *plane + x    ] = lrelu(d0);
            orow[(size_t)(co0 + 1)*plane + x    ] = lrelu(d1);
            orow[(size_t)co0      *plane + x + 8] = lrelu(d2);
            orow[(size_t)(co0 + 1)*plane + x + 8] = lrelu(d3);
        }
    }
}

// ---------------------------------------------------------------------------
// Launch
// ---------------------------------------------------------------------------
extern "C" void kernel_launch(void* const* d_in, const int* in_sizes, int n_in,
                              void* d_out, int out_size) {
    (void)in_sizes; (void)n_in; (void)out_size;
    const float* hrms = (const float*)d_in[0];
    const float* msi  = (const float*)d_in[1];
    const float* hsi  = (const float*)d_in[2];
    const float* Wv   = (const float*)d_in[3];
    const float* bv   = (const float*)d_in[4];
    const float* Wq   = (const float*)d_in[5];
    const float* bq   = (const float*)d_in[6];
    const float* Wk   = (const float*)d_in[7];
    const float* bk   = (const float*)d_in[8];
    const float* Wr   = (const float*)d_in[9];
    const float* br   = (const float*)d_in[10];
    float* out = (float*)d_out;

    cudaFuncSetAttribute(final_mma_kernel,
                         cudaFuncAttributeMaxDynamicSharedMemorySize, FINAL_SMEM);

    conv_v_kernel<<<dim3(16, 16, NB), 256>>>(hrms, Wv, bv);
    conv_q_kernel<<<64, 256>>>(msi, Wq, bq);
    qnorm_kernel<<<NB, 256>>>();
    im2col_k_kernel<<<dim3(KK9, NB), 256>>>(hsi);
    wrt_kernel<<<576, 256>>>(Wr);
    gemm_k_kernel<<<dim3(8, 2, NB*SPL), 256>>>(Wk);
    reduce_k_kernel<<<256, 256>>>(bk);
    att2_kernel<<<NB*CMS, 1024>>>();
    weff2_kernel<<<NB*CMS*9, 128>>>();
    final_mma_kernel<<<dim3(HH, NB), 256, FINAL_SMEM>>>(br, out);
}

// round 15
// speedup vs baseline: 1.8672x; 1.0675x over previous
#include <cuda_runtime.h>
#include <math.h>
#include <cstdint>

// ---------------------------------------------------------------------------
// Problem constants
// ---------------------------------------------------------------------------
#define NB   2
#define CMS  8
#define CHS  128
#define HH   512
#define HS   128
#define QS   32
#define KK9  (CHS*9)        // 1152 : conv_k im2col K
#define NPX  (QS*QS)        // 1024
#define SPL  8
#define KSP  (KK9/SPL)      // 144

typedef unsigned long long ull;

// ---------------------------------------------------------------------------
// Scratch
// ---------------------------------------------------------------------------
__device__ float g_v[NB*CMS*HH*HH];            // 16 MB
__device__ float g_q[NB*CMS*NPX];
__device__ float g_k[NB*CHS*NPX];
__device__ float g_k0max[NB];
__device__ float g_att[NB*CMS*CHS];
__device__ float g_weff[NB*CMS*9*CHS];         // [n][k=i*9+tap][co]
__device__ float g_kim[NB*KK9*NPX];
__device__ float g_kpart[SPL*NB*CHS*NPX];
__device__ float g_wrt[9*CHS*CHS];             // WrT[tap][c][co]

__device__ __forceinline__ float lrelu(float x) { return x >= 0.f ? x : 0.01f * x; }

#define FMA_F32X2(d, a, b, c) \
    asm("fma.rn.f32x2 %0, %1, %2, %3;" : "=l"(d) : "l"(a), "l"(b), "l"(c))
#define PACK2(out, lo, hi) \
    asm("mov.b64 %0, {%1, %2};" : "=l"(out) : "r"(lo), "r"(hi))
#define UNPACK2(lo, hi, in) \
    asm("mov.b64 {%0, %1}, %2;" : "=r"(lo), "=r"(hi) : "l"(in))
#define CVT_TF32(out, in) \
    asm("cvt.rna.tf32.f32 %0, %1;" : "=r"(out) : "f"(in))

// ---------------------------------------------------------------------------
// K1: conv_v  (8 -> 8, 3x3, stride 1, pad 1) + lrelu -> g_v   (f32x2 pairs)
// ---------------------------------------------------------------------------
__global__ void __launch_bounds__(256) conv_v_kernel(const float* __restrict__ x,
                                                     const float* __restrict__ Wv,
                                                     const float* __restrict__ bv) {
    __shared__ float s_in[8*34*36];
    __shared__ __align__(16) float s_w[8*9*8];
    int n  = blockIdx.z;
    int by = blockIdx.y * 32, bx = blockIdx.x * 32;
    int tid = threadIdx.x;

    for (int e = tid; e < 8*8*9; e += 256) {
        int co = e / 72, rem = e % 72;
        s_w[rem*8 + co] = Wv[e];
    }
    for (int e = tid; e < 8*34*34; e += 256) {
        int cin = e / 1156, rem = e % 1156, r = rem / 34, c = rem % 34;
        int gh = by - 1 + r, gw = bx - 1 + c;
        float v = 0.f;
        if ((unsigned)gh < (unsigned)HH && (unsigned)gw < (unsigned)HH)
            v = x[((n*CMS + cin)*HH + gh)*HH + gw];
        s_in[(cin*34 + r)*36 + c] = v;
    }
    __syncthreads();

    int lx = tid & 31, ly0 = (tid >> 5) * 4;
    ull accp[4][4];
    #pragma unroll
    for (int j = 0; j < 4; j++) {
        ull bj; PACK2(bj, __float_as_uint(bv[2*j]), __float_as_uint(bv[2*j+1]));
        #pragma unroll
        for (int p = 0; p < 4; p++) accp[j][p] = bj;
    }
    #pragma unroll
    for (int cin = 0; cin < 8; cin++) {
        ull vv[6][3];
        #pragma unroll
        for (int rr = 0; rr < 6; rr++)
            #pragma unroll
            for (int dx = 0; dx < 3; dx++) {
                unsigned u = __float_as_uint(s_in[(cin*34 + ly0 + rr)*36 + lx + dx]);
                PACK2(vv[rr][dx], u, u);
            }
        #pragma unroll
        for (int tap = 0; tap < 9; tap++) {
            int dy = tap / 3, dx = tap - dy*3;
            const ulonglong2* wp = (const ulonglong2*)&s_w[(cin*9 + tap)*8];
            ulonglong2 wa = wp[0], wb = wp[1];
            ull wj[4] = {wa.x, wa.y, wb.x, wb.y};
            #pragma unroll
            for (int p = 0; p < 4; p++)
                #pragma unroll
                for (int j = 0; j < 4; j++)
                    FMA_F32X2(accp[j][p], wj[j], vv[p + dy][dx], accp[j][p]);
        }
    }
    #pragma unroll
    for (int j = 0; j < 4; j++)
        #pragma unroll
        for (int p = 0; p < 4; p++) {
            unsigned lo, hi; UNPACK2(lo, hi, accp[j][p]);
            int row = by + ly0 + p;
            g_v[((n*CMS + 2*j    )*HH + row)*HH + bx + lx] = lrelu(__uint_as_float(lo));
            g_v[((n*CMS + 2*j + 1)*HH + row)*HH + bx + lx] = lrelu(__uint_as_float(hi));
        }
}

// ---------------------------------------------------------------------------
// K2: conv_q  (8 -> 8, 3x3, stride 16, pad 1) + lrelu     -> g_q
// ---------------------------------------------------------------------------
__global__ void __launch_bounds__(256) conv_q_kernel(const float* __restrict__ msi,
                                                     const float* __restrict__ Wq,
                                                     const float* __restrict__ bq) {
    int b = blockIdx.x;
    int n = b >> 5, i = (b >> 2) & 7, qy = b & 3;
    int tid = threadIdx.x;
    int ox = tid >> 3, ci = tid & 7;

    __shared__ float s_wq[72];
    if (tid < 72) s_wq[tid] = Wq[i*72 + tid];
    __syncthreads();

    float bias = bq[i];
    for (int r = 0; r < 8; r++) {
        int oy = qy*8 + r;
        float acc = 0.f;
        #pragma unroll
        for (int dy = 0; dy < 3; dy++) {
            int row = oy*16 + dy - 1;
            if ((unsigned)row >= (unsigned)HH) continue;
            #pragma unroll
            for (int dx = 0; dx < 3; dx++) {
                int col = ox*16 + dx - 1;
                if ((unsigned)col >= (unsigned)HH) continue;
                acc = fmaf(s_wq[ci*9 + dy*3 + dx],
                           msi[((n*CMS + ci)*HH + row)*HH + col], acc);
            }
        }
        acc += __shfl_xor_sync(0xffffffffu, acc, 1);
        acc += __shfl_xor_sync(0xffffffffu, acc, 2);
        acc += __shfl_xor_sync(0xffffffffu, acc, 4);
        if (ci == 0)
            g_q[((n*CMS + i)*QS + oy)*QS + ox] = lrelu(acc + bias);
    }
}

// ---------------------------------------------------------------------------
// K3: k0_max
// ---------------------------------------------------------------------------
__global__ void qnorm_kernel() {
    int n = blockIdx.x;
    int warp = threadIdx.x >> 5, lane = threadIdx.x & 31;
    const float* qp = g_q + (n*CMS + warp)*NPX;
    float s = 0.f;
    for (int j = lane; j < NPX; j += 32) { float v = qp[j]; s += v*v; }
    #pragma unroll
    for (int o = 16; o; o >>= 1) s += __shfl_xor_sync(0xffffffffu, s, o);
    __shared__ float sn[8];
    if (lane == 0) sn[warp] = sqrtf(s);
    __syncthreads();
    if (threadIdx.x == 0) {
        float m = sn[0];
        #pragma unroll
        for (int i = 1; i < 8; i++) m = fmaxf(m, sn[i]);
        g_k0max[n] = m;
    }
}

// ---------------------------------------------------------------------------
// K4a: im2col for conv_k
// ---------------------------------------------------------------------------
__global__ void __launch_bounds__(256) im2col_k_kernel(const float* __restrict__ hsi) {
    int k = blockIdx.x;
    int n = blockIdx.y;
    int ci = k / 9, tap = k % 9;
    int dy = tap / 3, dx = tap % 3;
    const float* src = hsi + (n*CHS + ci)*HS*HS;
    float* dst = g_kim + (n*KK9 + k)*NPX;
    for (int px = threadIdx.x; px < NPX; px += 256) {
        int oy = px >> 5, ox = px & 31;
        int row = 4*oy + dy - 1, col = 4*ox + dx - 1;
        float v = 0.f;
        if ((unsigned)row < (unsigned)HS && (unsigned)col < (unsigned)HS)
            v = src[row*HS + col];
        dst[px] = v;
    }
}

// ---------------------------------------------------------------------------
// K4b: split-K GEMM for conv_k (f32x2)
// ---------------------------------------------------------------------------
__global__ void __launch_bounds__(256) gemm_k_kernel(const float* __restrict__ Wk) {
    __shared__ __align__(16) float s_w[16*68];
    __shared__ __align__(16) float s_im[16*128];
    int px0 = blockIdx.x * 128;
    int co0 = blockIdx.y * 64;
    int z = blockIdx.z;
    int n = z >> 3, s = z & 7;
    int k0 = s * KSP;
    int tid = threadIdx.x;
    int c8 = tid >> 5, pxq = tid & 31;

    ull acc[4][4];
    #pragma unroll
    for (int j = 0; j < 4; j++)
        #pragma unroll
        for (int p = 0; p < 4; p++) acc[j][p] = 0ull;

    for (int cc = 0; cc < KSP/16; cc++) {
        int kbase = k0 + cc*16;
        #pragma unroll
        for (int e = tid; e < 1024; e += 256) {
            int co = e >> 4, kk = e & 15;
            s_w[kk*68 + co] = Wk[(co0 + co)*KK9 + kbase + kk];
        }
        #pragma unroll
        for (int e = tid; e < 2048; e += 256) {
            int kk = e >> 7, p = e & 127;
            s_im[kk*128 + p] = g_kim[(n*KK9 + kbase + kk)*NPX + px0 + p];
        }
        __syncthreads();
        #pragma unroll
        for (int kk = 0; kk < 16; kk++) {
            const ulonglong2* wp = (const ulonglong2*)&s_w[kk*68 + c8*8];
            ulonglong2 wa = wp[0], wb = wp[1];
            ull wj[4] = {wa.x, wa.y, wb.x, wb.y};
            float4 im = *(const float4*)&s_im[kk*128 + pxq*4];
            float imv[4] = {im.x, im.y, im.z, im.w};
            #pragma unroll
            for (int p = 0; p < 4; p++) {
                unsigned u = __float_as_uint(imv[p]);
                ull vv; PACK2(vv, u, u);
                #pragma unroll
                for (int j = 0; j < 4; j++)
                    FMA_F32X2(acc[j][p], wj[j], vv, acc[j][p]);
            }
        }
        __syncthreads();
    }

    int pbase = (s*NB + n)*CHS;
    #pragma unroll
    for (int j = 0; j < 4; j++) {
        int co = co0 + c8*8 + 2*j;
        #pragma unroll
        for (int p = 0; p < 4; p++) {
            unsigned lo, hi; UNPACK2(lo, hi, acc[j][p]);
            int px = px0 + pxq*4 + p;
            g_kpart[(pbase + co    )*NPX + px] = __uint_as_float(lo);
            g_kpart[(pbase + co + 1)*NPX + px] = __uint_as_float(hi);
        }
    }
}

// ---------------------------------------------------------------------------
// K4c: reduce split-K partials + bias + lrelu -> g_k
// ---------------------------------------------------------------------------
__global__ void __launch_bounds__(256) reduce_k_kernel(const float* __restrict__ bk) {
    int idx4 = blockIdx.x * 256 + threadIdx.x;
    int idx = idx4 * 4;
    int co = (idx >> 10) & 127;
    float4 sum = make_float4(0.f, 0.f, 0.f, 0.f);
    #pragma unroll
    for (int s = 0; s < SPL; s++) {
        float4 v = ((const float4*)g_kpart)[s*65536 + idx4];
        sum.x += v.x; sum.y += v.y; sum.z += v.z; sum.w += v.w;
    }
    float b = bk[co];
    float4 o;
    o.x = lrelu(sum.x + b); o.y = lrelu(sum.y + b);
    o.z = lrelu(sum.z + b); o.w = lrelu(sum.w + b);
    ((float4*)g_k)[idx4] = o;
}

// ---------------------------------------------------------------------------
// K5a: Wr transpose -> WrT[tap][c][co]
// ---------------------------------------------------------------------------
__global__ void __launch_bounds__(256) wrt_kernel(const float* __restrict__ Wr) {
    int e = blockIdx.x * 256 + threadIdx.x;
    if (e >= 9*CHS*CHS) return;
    int co = e / (CHS*9), rem = e % (CHS*9), c = rem / 9, tap = rem % 9;
    g_wrt[(tap*CHS + c)*CHS + co] = Wr[e];
}

// ---------------------------------------------------------------------------
// K5b: att2 — block per b (16 x 1024): 8 lanes per channel, coalesced dot.
// ---------------------------------------------------------------------------
__global__ void __launch_bounds__(1024) att2_kernel() {
    __shared__ __align__(16) float s_q[NPX];
    __shared__ float s_red[128];
    __shared__ float s_sc[2];

    int b = blockIdx.x, n = b >> 3;
    int tid = threadIdx.x;
    int c = tid >> 3, t8 = tid & 7;

    s_q[tid] = g_q[b*NPX + tid];
    __syncthreads();

    const float4* kp = (const float4*)(g_k + (n*CHS + c)*NPX);
    const float4* qp = (const float4*)s_q;
    float acc = 0.f;
    #pragma unroll 8
    for (int j = 0; j < 32; j++) {
        int i4 = t8 + j*8;
        float4 kv = kp[i4], qv = qp[i4];
        acc += kv.x*qv.x + kv.y*qv.y + kv.z*qv.z + kv.w*qv.w;
    }
    acc += __shfl_xor_sync(0xffffffffu, acc, 1);
    acc += __shfl_xor_sync(0xffffffffu, acc, 2);
    acc += __shfl_xor_sync(0xffffffffu, acc, 4);
    if (t8 == 0) s_red[c] = acc;
    __syncthreads();

    float s = 0.f;
    if (tid < 128) { s = s_red[tid] * (10.0f / g_k0max[n]); s_red[tid] = s; }
    __syncthreads();
    for (int off = 64; off; off >>= 1) {
        if (tid < off) s_red[tid] = fmaxf(s_red[tid], s_red[tid + off]);
        __syncthreads();
    }
    if (tid == 0) s_sc[0] = s_red[0];
    __syncthreads();
    float e = 0.f;
    if (tid < 128) { e = expf(s - s_sc[0]); s_red[tid] = e; }
    __syncthreads();
    for (int off = 64; off; off >>= 1) {
        if (tid < off) s_red[tid] += s_red[tid + off];
        __syncthreads();
    }
    if (tid == 0) s_sc[1] = s_red[0];
    __syncthreads();
    if (tid < 128) g_att[b*CHS + tid] = e / s_sc[1];
}

// ---------------------------------------------------------------------------
// K5c: weff2 — block per (b, tap); WrT reads coalesced, L2-resident.
// ---------------------------------------------------------------------------
__global__ void __launch_bounds__(128) weff2_kernel() {
    __shared__ float s_att[128];
    int bid = blockIdx.x;
    int b = bid / 9, tap = bid % 9;
    int co = threadIdx.x;
    s_att[co] = g_att[b*CHS + co];
    __syncthreads();
    const float* wp = g_wrt + tap*CHS*CHS + co;
    float acc = 0.f;
    #pragma unroll 8
    for (int c = 0; c < 128; c++)
        acc = fmaf(s_att[c], wp[c*CHS], acc);
    g_weff[(b*9 + tap)*CHS + co] = acc * (1.0f/6.0f);
}

// ---------------------------------------------------------------------------
// K7: final conv via mma.sync tf32.  M=32 px per warp iteration: two m16
//   tiles share every B-fragment read -> B smem traffic halved vs M=16.
// ---------------------------------------------------------------------------
#define HALO_STRIDE 516
#define HALO_FLOATS (8*3*HALO_STRIDE)     // 12384
#define BSTR 136
#define B_FLOATS (72*BSTR)                // 9792
#define FINAL_SMEM ((HALO_FLOATS + B_FLOATS + 128) * 4)   // 89216 B

__global__ void __launch_bounds__(256, 2) final_mma_kernel(const float* __restrict__ br,
                                                           float* __restrict__ out) {
    extern __shared__ float sm[];
    float*    s_halo = sm;                                   // 12384 floats
    uint32_t* s_B    = (uint32_t*)(sm + HALO_FLOATS);        // 9792 (tf32)
    float*    s_br   = sm + HALO_FLOATS + B_FLOATS;          // 128

    int y = blockIdx.x;
    int n = blockIdx.y;
    int tid = threadIdx.x;
    int lane = tid & 31, w = tid >> 5;
    int q = lane & 3, r = lane >> 2;

    // --- B = Weff (tf32) into smem [k][co], stride 136 ---
    const float* wsrc = g_weff + n*72*128;
    for (int e = tid; e < 72*128; e += 256) {
        int k = e >> 7, co = e & 127;
        uint32_t t; CVT_TF32(t, wsrc[k*128 + co]);
        s_B[k*BSTR + co] = t;
    }
    if (tid < 128) s_br[tid] = br[tid];

    // --- halo: 8 cin x 3 rows x 514 cols ---
    for (int e = tid; e < 8*3*514; e += 256) {
        int cin = e / 1542, rem = e % 1542, rr = rem / 514, cc = rem % 514;
        int gh = y - 1 + rr, gw = cc - 1;
        float v = 0.f;
        if ((unsigned)gh < (unsigned)HH && (unsigned)gw < (unsigned)HH)
            v = g_v[((n*CMS + cin)*HH + gh)*HH + gw];
        s_halo[(cin*3 + rr)*HALO_STRIDE + cc] = v;
    }
    __syncthreads();

    // --- per-lane k -> halo-offset tables (k = kk*8 + q (+4)) ---
    int off0[9], off1[9];
    #pragma unroll
    for (int kk = 0; kk < 9; kk++) {
        int k = kk*8 + q;
        int cin = k / 9, tap = k % 9;
        off0[kk] = (cin*3 + tap/3)*HALO_STRIDE + (tap%3);
        k += 4; cin = k / 9; tap = k % 9;
        off1[kk] = (cin*3 + tap/3)*HALO_STRIDE + (tap%3);
    }

    float* orow = out + (size_t)(n*CHS) * (HH*HH) + (size_t)y * HH;
    const size_t plane = (size_t)HH * HH;

    // warp covers px [w*64, w*64+64); i selects 32-px half (two m16 tiles)
    #pragma unroll
    for (int i = 0; i < 2; i++) {
        int x = w*64 + i*32 + r;     // tile0 lane px; tile1 at x+16

        // A fragments: 9 kk x (tile0: 4, tile1: 4)
        uint32_t a[9][8];
        #pragma unroll
        for (int kk = 0; kk < 9; kk++) {
            CVT_TF32(a[kk][0], s_halo[off0[kk] + x]);
            CVT_TF32(a[kk][1], s_halo[off0[kk] + x + 8]);
            CVT_TF32(a[kk][2], s_halo[off1[kk] + x]);
            CVT_TF32(a[kk][3], s_halo[off1[kk] + x + 8]);
            CVT_TF32(a[kk][4], s_halo[off0[kk] + x + 16]);
            CVT_TF32(a[kk][5], s_halo[off0[kk] + x + 24]);
            CVT_TF32(a[kk][6], s_halo[off1[kk] + x + 16]);
            CVT_TF32(a[kk][7], s_halo[off1[kk] + x + 24]);
        }

        for (int nt = 0; nt < 16; nt++) {
            int n0  = nt * 8;
            int co0 = n0 + 2*q;
            float bi0 = s_br[co0], bi1 = s_br[co0 + 1];
            float d0 = bi0, d1 = bi1, d2 = bi0, d3 = bi1;   // tile0
            float e0 = bi0, e1 = bi1, e2 = bi0, e3 = bi1;   // tile1
            const uint32_t* bp = &s_B[q*BSTR + n0 + r];
            #pragma unroll
            for (int kk = 0; kk < 9; kk++) {
                uint32_t b0 = bp[(kk*8    )*BSTR];
                uint32_t b1 = bp[(kk*8 + 4)*BSTR];
                asm("mma.sync.aligned.m16n8k8.row.col.f32.tf32.tf32.f32 "
                    "{%0,%1,%2,%3}, {%4,%5,%6,%7}, {%8,%9}, {%0,%1,%2,%3};"
                    : "+f"(d0), "+f"(d1), "+f"(d2), "+f"(d3)
                    : "r"(a[kk][0]), "r"(a[kk][1]), "r"(a[kk][2]), "r"(a[kk][3]),
                      "r"(b0), "r"(b1));
                asm("mma.sync.aligned.m16n8k8.row.col.f32.tf32.tf32.f32 "
                    "{%0,%1,%2,%3}, {%4,%5,%6,%7}, {%8,%9}, {%0,%1,%2,%3};"
                    : "+f"(e0), "+f"(e1), "+f"(e2), "+f"(e3)
                    : "r"(a[kk][4]), "r"(a[kk][5]), "r"(a[kk][6]), "r"(a[kk][7]),
                      "r"(b0), "r"(b1));
            }
            float* p0 = orow + (size_t)co0      *plane + x;
            float* p1 = orow + (size_t)(co0 + 1)*plane + x;
            p0[0]  = lrelu(d0);  p1[0]  = lrelu(d1);
            p0[8]  = lrelu(d2);  p1[8]  = lrelu(d3);
            p0[16] = lrelu(e0);  p1[16] = lrelu(e1);
            p0[24] = lrelu(e2);  p1[24] = lrelu(e3);
        }
    }
}

// ---------------------------------------------------------------------------
// Launch
// ---------------------------------------------------------------------------
extern "C" void kernel_launch(void* const* d_in, const int* in_sizes, int n_in,
                              void* d_out, int out_size) {
    (void)in_sizes; (void)n_in; (void)out_size;
    const float* hrms = (const float*)d_in[0];
    const float* msi  = (const float*)d_in[1];
    const float* hsi  = (const float*)d_in[2];
    const float* Wv   = (const float*)d_in[3];
    const float* bv   = (const float*)d_in[4];
    const float* Wq   = (const float*)d_in[5];
    const float* bq   = (const float*)d_in[6];
    const float* Wk   = (const float*)d_in[7];
    const float* bk   = (const float*)d_in[8];
    const float* Wr   = (const float*)d_in[9];
    const float* br   = (const float*)d_in[10];
    float* out = (float*)d_out;

    cudaFuncSetAttribute(final_mma_kernel,
                         cudaFuncAttributeMaxDynamicSharedMemorySize, FINAL_SMEM);

    conv_v_kernel<<<dim3(16, 16, NB), 256>>>(hrms, Wv, bv);
    conv_q_kernel<<<64, 256>>>(msi, Wq, bq);
    qnorm_kernel<<<NB, 256>>>();
    im2col_k_kernel<<<dim3(KK9, NB), 256>>>(hsi);
    wrt_kernel<<<576, 256>>>(Wr);
    gemm_k_kernel<<<dim3(8, 2, NB*SPL), 256>>>(Wk);
    reduce_k_kernel<<<256, 256>>>(bk);
    att2_kernel<<<NB*CMS, 1024>>>();
    weff2_kernel<<<NB*CMS*9, 128>>>();
    final_mma_kernel<<<dim3(HH, NB), 256, FINAL_SMEM>>>(br, out);
}

// round 16
// speedup vs baseline: 1.9301x; 1.0337x over previous
#include <cuda_runtime.h>
#include <math.h>
#include <cstdint>

// ---------------------------------------------------------------------------
// Problem constants
// ---------------------------------------------------------------------------
#define NB   2
#define CMS  8
#define CHS  128
#define HH   512
#define HS   128
#define QS   32
#define KK9  (CHS*9)        // 1152 : conv_k im2col K
#define NPX  (QS*QS)        // 1024
#define SPL  8
#define KSP  (KK9/SPL)      // 144

typedef unsigned long long ull;

// ---------------------------------------------------------------------------
// Scratch
// ---------------------------------------------------------------------------
__device__ float g_v[NB*CMS*HH*HH];            // 16 MB
__device__ float g_q[NB*CMS*NPX];
__device__ float g_k[NB*CHS*NPX];
__device__ float g_k0max[NB];
__device__ float g_att[NB*CMS*CHS];
__device__ float g_weff[NB*CMS*9*CHS];         // [n][k=i*9+tap][co]
__device__ float g_kim[NB*KK9*NPX];
__device__ float g_kpart[SPL*NB*CHS*NPX];
__device__ float g_wrt[9*CHS*CHS];             // WrT[tap][c][co]

__device__ __forceinline__ float lrelu(float x) { return x >= 0.f ? x : 0.01f * x; }

#define FMA_F32X2(d, a, b, c) \
    asm("fma.rn.f32x2 %0, %1, %2, %3;" : "=l"(d) : "l"(a), "l"(b), "l"(c))
#define PACK2(out, lo, hi) \
    asm("mov.b64 %0, {%1, %2};" : "=l"(out) : "r"(lo), "r"(hi))
#define UNPACK2(lo, hi, in) \
    asm("mov.b64 {%0, %1}, %2;" : "=r"(lo), "=r"(hi) : "l"(in))
#define CVT_TF32(out, in) \
    asm("cvt.rna.tf32.f32 %0, %1;" : "=r"(out) : "f"(in))

// ---------------------------------------------------------------------------
// K1: conv_v  (8 -> 8, 3x3, stride 1, pad 1) + lrelu -> g_v   (f32x2 pairs)
// ---------------------------------------------------------------------------
__global__ void __launch_bounds__(256) conv_v_kernel(const float* __restrict__ x,
                                                     const float* __restrict__ Wv,
                                                     const float* __restrict__ bv) {
    __shared__ float s_in[8*34*36];
    __shared__ __align__(16) float s_w[8*9*8];
    int n  = blockIdx.z;
    int by = blockIdx.y * 32, bx = blockIdx.x * 32;
    int tid = threadIdx.x;

    for (int e = tid; e < 8*8*9; e += 256) {
        int co = e / 72, rem = e % 72;
        s_w[rem*8 + co] = Wv[e];
    }
    for (int e = tid; e < 8*34*34; e += 256) {
        int cin = e / 1156, rem = e % 1156, r = rem / 34, c = rem % 34;
        int gh = by - 1 + r, gw = bx - 1 + c;
        float v = 0.f;
        if ((unsigned)gh < (unsigned)HH && (unsigned)gw < (unsigned)HH)
            v = x[((n*CMS + cin)*HH + gh)*HH + gw];
        s_in[(cin*34 + r)*36 + c] = v;
    }
    __syncthreads();

    int lx = tid & 31, ly0 = (tid >> 5) * 4;
    ull accp[4][4];
    #pragma unroll
    for (int j = 0; j < 4; j++) {
        ull bj; PACK2(bj, __float_as_uint(bv[2*j]), __float_as_uint(bv[2*j+1]));
        #pragma unroll
        for (int p = 0; p < 4; p++) accp[j][p] = bj;
    }
    #pragma unroll
    for (int cin = 0; cin < 8; cin++) {
        ull vv[6][3];
        #pragma unroll
        for (int rr = 0; rr < 6; rr++)
            #pragma unroll
            for (int dx = 0; dx < 3; dx++) {
                unsigned u = __float_as_uint(s_in[(cin*34 + ly0 + rr)*36 + lx + dx]);
                PACK2(vv[rr][dx], u, u);
            }
        #pragma unroll
        for (int tap = 0; tap < 9; tap++) {
            int dy = tap / 3, dx = tap - dy*3;
            const ulonglong2* wp = (const ulonglong2*)&s_w[(cin*9 + tap)*8];
            ulonglong2 wa = wp[0], wb = wp[1];
            ull wj[4] = {wa.x, wa.y, wb.x, wb.y};
            #pragma unroll
            for (int p = 0; p < 4; p++)
                #pragma unroll
                for (int j = 0; j < 4; j++)
                    FMA_F32X2(accp[j][p], wj[j], vv[p + dy][dx], accp[j][p]);
        }
    }
    #pragma unroll
    for (int j = 0; j < 4; j++)
        #pragma unroll
        for (int p = 0; p < 4; p++) {
            unsigned lo, hi; UNPACK2(lo, hi, accp[j][p]);
            int row = by + ly0 + p;
            g_v[((n*CMS + 2*j    )*HH + row)*HH + bx + lx] = lrelu(__uint_as_float(lo));
            g_v[((n*CMS + 2*j + 1)*HH + row)*HH + bx + lx] = lrelu(__uint_as_float(hi));
        }
}

// ---------------------------------------------------------------------------
// K2: conv_q  (8 -> 8, 3x3, stride 16, pad 1) + lrelu     -> g_q
// ---------------------------------------------------------------------------
__global__ void __launch_bounds__(256) conv_q_kernel(const float* __restrict__ msi,
                                                     const float* __restrict__ Wq,
                                                     const float* __restrict__ bq) {
    int b = blockIdx.x;
    int n = b >> 5, i = (b >> 2) & 7, qy = b & 3;
    int tid = threadIdx.x;
    int ox = tid >> 3, ci = tid & 7;

    __shared__ float s_wq[72];
    if (tid < 72) s_wq[tid] = Wq[i*72 + tid];
    __syncthreads();

    float bias = bq[i];
    for (int r = 0; r < 8; r++) {
        int oy = qy*8 + r;
        float acc = 0.f;
        #pragma unroll
        for (int dy = 0; dy < 3; dy++) {
            int row = oy*16 + dy - 1;
            if ((unsigned)row >= (unsigned)HH) continue;
            #pragma unroll
            for (int dx = 0; dx < 3; dx++) {
                int col = ox*16 + dx - 1;
                if ((unsigned)col >= (unsigned)HH) continue;
                acc = fmaf(s_wq[ci*9 + dy*3 + dx],
                           msi[((n*CMS + ci)*HH + row)*HH + col], acc);
            }
        }
        acc += __shfl_xor_sync(0xffffffffu, acc, 1);
        acc += __shfl_xor_sync(0xffffffffu, acc, 2);
        acc += __shfl_xor_sync(0xffffffffu, acc, 4);
        if (ci == 0)
            g_q[((n*CMS + i)*QS + oy)*QS + ox] = lrelu(acc + bias);
    }
}

// ---------------------------------------------------------------------------
// K3: k0_max
// ---------------------------------------------------------------------------
__global__ void qnorm_kernel() {
    int n = blockIdx.x;
    int warp = threadIdx.x >> 5, lane = threadIdx.x & 31;
    const float* qp = g_q + (n*CMS + warp)*NPX;
    float s = 0.f;
    for (int j = lane; j < NPX; j += 32) { float v = qp[j]; s += v*v; }
    #pragma unroll
    for (int o = 16; o; o >>= 1) s += __shfl_xor_sync(0xffffffffu, s, o);
    __shared__ float sn[8];
    if (lane == 0) sn[warp] = sqrtf(s);
    __syncthreads();
    if (threadIdx.x == 0) {
        float m = sn[0];
        #pragma unroll
        for (int i = 1; i < 8; i++) m = fmaxf(m, sn[i]);
        g_k0max[n] = m;
    }
}

// ---------------------------------------------------------------------------
// K4a: im2col for conv_k
// ---------------------------------------------------------------------------
__global__ void __launch_bounds__(256) im2col_k_kernel(const float* __restrict__ hsi) {
    int k = blockIdx.x;
    int n = blockIdx.y;
    int ci = k / 9, tap = k % 9;
    int dy = tap / 3, dx = tap % 3;
    const float* src = hsi + (n*CHS + ci)*HS*HS;
    float* dst = g_kim + (n*KK9 + k)*NPX;
    for (int px = threadIdx.x; px < NPX; px += 256) {
        int oy = px >> 5, ox = px & 31;
        int row = 4*oy + dy - 1, col = 4*ox + dx - 1;
        float v = 0.f;
        if ((unsigned)row < (unsigned)HS && (unsigned)col < (unsigned)HS)
            v = src[row*HS + col];
        dst[px] = v;
    }
}

// ---------------------------------------------------------------------------
// K4b: split-K GEMM for conv_k (f32x2)
// ---------------------------------------------------------------------------
__global__ void __launch_bounds__(256) gemm_k_kernel(const float* __restrict__ Wk) {
    __shared__ __align__(16) float s_w[16*68];
    __shared__ __align__(16) float s_im[16*128];
    int px0 = blockIdx.x * 128;
    int co0 = blockIdx.y * 64;
    int z = blockIdx.z;
    int n = z >> 3, s = z & 7;
    int k0 = s * KSP;
    int tid = threadIdx.x;
    int c8 = tid >> 5, pxq = tid & 31;

    ull acc[4][4];
    #pragma unroll
    for (int j = 0; j < 4; j++)
        #pragma unroll
        for (int p = 0; p < 4; p++) acc[j][p] = 0ull;

    for (int cc = 0; cc < KSP/16; cc++) {
        int kbase = k0 + cc*16;
        #pragma unroll
        for (int e = tid; e < 1024; e += 256) {
            int co = e >> 4, kk = e & 15;
            s_w[kk*68 + co] = Wk[(co0 + co)*KK9 + kbase + kk];
        }
        #pragma unroll
        for (int e = tid; e < 2048; e += 256) {
            int kk = e >> 7, p = e & 127;
            s_im[kk*128 + p] = g_kim[(n*KK9 + kbase + kk)*NPX + px0 + p];
        }
        __syncthreads();
        #pragma unroll
        for (int kk = 0; kk < 16; kk++) {
            const ulonglong2* wp = (const ulonglong2*)&s_w[kk*68 + c8*8];
            ulonglong2 wa = wp[0], wb = wp[1];
            ull wj[4] = {wa.x, wa.y, wb.x, wb.y};
            float4 im = *(const float4*)&s_im[kk*128 + pxq*4];
            float imv[4] = {im.x, im.y, im.z, im.w};
            #pragma unroll
            for (int p = 0; p < 4; p++) {
                unsigned u = __float_as_uint(imv[p]);
                ull vv; PACK2(vv, u, u);
                #pragma unroll
                for (int j = 0; j < 4; j++)
                    FMA_F32X2(acc[j][p], wj[j], vv, acc[j][p]);
            }
        }
        __syncthreads();
    }

    int pbase = (s*NB + n)*CHS;
    #pragma unroll
    for (int j = 0; j < 4; j++) {
        int co = co0 + c8*8 + 2*j;
        #pragma unroll
        for (int p = 0; p < 4; p++) {
            unsigned lo, hi; UNPACK2(lo, hi, acc[j][p]);
            int px = px0 + pxq*4 + p;
            g_kpart[(pbase + co    )*NPX + px] = __uint_as_float(lo);
            g_kpart[(pbase + co + 1)*NPX + px] = __uint_as_float(hi);
        }
    }
}

// ---------------------------------------------------------------------------
// K4c: reduce split-K partials + bias + lrelu -> g_k
// ---------------------------------------------------------------------------
__global__ void __launch_bounds__(256) reduce_k_kernel(const float* __restrict__ bk) {
    int idx4 = blockIdx.x * 256 + threadIdx.x;
    int idx = idx4 * 4;
    int co = (idx >> 10) & 127;
    float4 sum = make_float4(0.f, 0.f, 0.f, 0.f);
    #pragma unroll
    for (int s = 0; s < SPL; s++) {
        float4 v = ((const float4*)g_kpart)[s*65536 + idx4];
        sum.x += v.x; sum.y += v.y; sum.z += v.z; sum.w += v.w;
    }
    float b = bk[co];
    float4 o;
    o.x = lrelu(sum.x + b); o.y = lrelu(sum.y + b);
    o.z = lrelu(sum.z + b); o.w = lrelu(sum.w + b);
    ((float4*)g_k)[idx4] = o;
}

// ---------------------------------------------------------------------------
// K5a: Wr transpose -> WrT[tap][c][co]
// ---------------------------------------------------------------------------
__global__ void __launch_bounds__(256) wrt_kernel(const float* __restrict__ Wr) {
    int e = blockIdx.x * 256 + threadIdx.x;
    if (e >= 9*CHS*CHS) return;
    int co = e / (CHS*9), rem = e % (CHS*9), c = rem / 9, tap = rem % 9;
    g_wrt[(tap*CHS + c)*CHS + co] = Wr[e];
}

// ---------------------------------------------------------------------------
// K5b: att2 — block per b (16 x 1024): 8 lanes per channel, coalesced dot.
// ---------------------------------------------------------------------------
__global__ void __launch_bounds__(1024) att2_kernel() {
    __shared__ __align__(16) float s_q[NPX];
    __shared__ float s_red[128];
    __shared__ float s_sc[2];

    int b = blockIdx.x, n = b >> 3;
    int tid = threadIdx.x;
    int c = tid >> 3, t8 = tid & 7;

    s_q[tid] = g_q[b*NPX + tid];
    __syncthreads();

    const float4* kp = (const float4*)(g_k + (n*CHS + c)*NPX);
    const float4* qp = (const float4*)s_q;
    float acc = 0.f;
    #pragma unroll 8
    for (int j = 0; j < 32; j++) {
        int i4 = t8 + j*8;
        float4 kv = kp[i4], qv = qp[i4];
        acc += kv.x*qv.x + kv.y*qv.y + kv.z*qv.z + kv.w*qv.w;
    }
    acc += __shfl_xor_sync(0xffffffffu, acc, 1);
    acc += __shfl_xor_sync(0xffffffffu, acc, 2);
    acc += __shfl_xor_sync(0xffffffffu, acc, 4);
    if (t8 == 0) s_red[c] = acc;
    __syncthreads();

    float s = 0.f;
    if (tid < 128) { s = s_red[tid] * (10.0f / g_k0max[n]); s_red[tid] = s; }
    __syncthreads();
    for (int off = 64; off; off >>= 1) {
        if (tid < off) s_red[tid] = fmaxf(s_red[tid], s_red[tid + off]);
        __syncthreads();
    }
    if (tid == 0) s_sc[0] = s_red[0];
    __syncthreads();
    float e = 0.f;
    if (tid < 128) { e = expf(s - s_sc[0]); s_red[tid] = e; }
    __syncthreads();
    for (int off = 64; off; off >>= 1) {
        if (tid < off) s_red[tid] += s_red[tid + off];
        __syncthreads();
    }
    if (tid == 0) s_sc[1] = s_red[0];
    __syncthreads();
    if (tid < 128) g_att[b*CHS + tid] = e / s_sc[1];
}

// ---------------------------------------------------------------------------
// K5c: weff2 — block per (b, tap); WrT reads coalesced, L2-resident.
// ---------------------------------------------------------------------------
__global__ void __launch_bounds__(128) weff2_kernel() {
    __shared__ float s_att[128];
    int bid = blockIdx.x;
    int b = bid / 9, tap = bid % 9;
    int co = threadIdx.x;
    s_att[co] = g_att[b*CHS + co];
    __syncthreads();
    const float* wp = g_wrt + tap*CHS*CHS + co;
    float acc = 0.f;
    #pragma unroll 8
    for (int c = 0; c < 128; c++)
        acc = fmaf(s_att[c], wp[c*CHS], acc);
    g_weff[(b*9 + tap)*CHS + co] = acc * (1.0f/6.0f);
}

// ---------------------------------------------------------------------------
// K7: final conv via mma.sync tf32.  M=32 px per warp iteration, TWO output
//   rows per CTA (B build halved per row, halo 2 rows/output vs 3), streaming
//   stores (__stcs) for the write-once output.
// ---------------------------------------------------------------------------
#define HALO_STRIDE 516
#define HALO_ROWS   4
#define HALO_FLOATS (8*HALO_ROWS*HALO_STRIDE)   // 16512
#define BSTR 136
#define B_FLOATS (72*BSTR)                      // 9792
#define FINAL_SMEM ((HALO_FLOATS + B_FLOATS + 128) * 4)   // 105728 B

__global__ void __launch_bounds__(256, 2) final_mma_kernel(const float* __restrict__ br,
                                                           float* __restrict__ out) {
    extern __shared__ float sm[];
    float*    s_halo = sm;                                   // 16512 floats
    uint32_t* s_B    = (uint32_t*)(sm + HALO_FLOATS);        // 9792 (tf32)
    float*    s_br   = sm + HALO_FLOATS + B_FLOATS;          // 128

    int y0 = blockIdx.x * 2;
    int n = blockIdx.y;
    int tid = threadIdx.x;
    int lane = tid & 31, w = tid >> 5;
    int q = lane & 3, r = lane >> 2;

    // --- B = Weff (tf32) into smem [k][co], stride 136 ---
    const float* wsrc = g_weff + n*72*128;
    for (int e = tid; e < 72*128; e += 256) {
        int k = e >> 7, co = e & 127;
        uint32_t t; CVT_TF32(t, wsrc[k*128 + co]);
        s_B[k*BSTR + co] = t;
    }
    if (tid < 128) s_br[tid] = br[tid];

    // --- halo: 8 cin x 4 rows x 514 cols (rows y0-1 .. y0+2) ---
    for (int e = tid; e < 8*HALO_ROWS*514; e += 256) {
        int cin = e / (HALO_ROWS*514), rem = e % (HALO_ROWS*514);
        int rr = rem / 514, cc = rem % 514;
        int gh = y0 - 1 + rr, gw = cc - 1;
        float v = 0.f;
        if ((unsigned)gh < (unsigned)HH && (unsigned)gw < (unsigned)HH)
            v = g_v[((n*CMS + cin)*HH + gh)*HH + gw];
        s_halo[(cin*HALO_ROWS + rr)*HALO_STRIDE + cc] = v;
    }
    __syncthreads();

    // --- per-lane k -> halo-offset tables (row-independent part) ---
    int off0[9], off1[9];
    #pragma unroll
    for (int kk = 0; kk < 9; kk++) {
        int k = kk*8 + q;
        int cin = k / 9, tap = k % 9;
        off0[kk] = (cin*HALO_ROWS + tap/3)*HALO_STRIDE + (tap%3);
        k += 4; cin = k / 9; tap = k % 9;
        off1[kk] = (cin*HALO_ROWS + tap/3)*HALO_STRIDE + (tap%3);
    }

    const size_t plane = (size_t)HH * HH;
    float* obase = out + (size_t)(n*CHS) * plane;

    // 4 warp-iters: yr = i>>1 (output row), xhalf = i&1 (32-px half of w's 64)
    #pragma unroll
    for (int i = 0; i < 4; i++) {
        int yr = i >> 1;
        int yofs = yr * HALO_STRIDE;
        int x = w*64 + (i & 1)*32 + r;   // tile0 lane px; tile1 at x+16
        float* orow = obase + (size_t)(y0 + yr) * HH;

        // A fragments: 9 kk x (tile0: 4, tile1: 4)
        uint32_t a[9][8];
        #pragma unroll
        for (int kk = 0; kk < 9; kk++) {
            CVT_TF32(a[kk][0], s_halo[off0[kk] + yofs + x]);
            CVT_TF32(a[kk][1], s_halo[off0[kk] + yofs + x + 8]);
            CVT_TF32(a[kk][2], s_halo[off1[kk] + yofs + x]);
            CVT_TF32(a[kk][3], s_halo[off1[kk] + yofs + x + 8]);
            CVT_TF32(a[kk][4], s_halo[off0[kk] + yofs + x + 16]);
            CVT_TF32(a[kk][5], s_halo[off0[kk] + yofs + x + 24]);
            CVT_TF32(a[kk][6], s_halo[off1[kk] + yofs + x + 16]);
            CVT_TF32(a[kk][7], s_halo[off1[kk] + yofs + x + 24]);
        }

        for (int nt = 0; nt < 16; nt++) {
            int n0  = nt * 8;
            int co0 = n0 + 2*q;
            float2 bi = *(const float2*)&s_br[co0];
            float d0 = bi.x, d1 = bi.y, d2 = bi.x, d3 = bi.y;   // tile0
            float e0 = bi.x, e1 = bi.y, e2 = bi.x, e3 = bi.y;   // tile1
            const uint32_t* bp = &s_B[q*BSTR + n0 + r];
            #pragma unroll
            for (int kk = 0; kk < 9; kk++) {
                uint32_t b0 = bp[(kk*8    )*BSTR];
                uint32_t b1 = bp[(kk*8 + 4)*BSTR];
                asm("mma.sync.aligned.m16n8k8.row.col.f32.tf32.tf32.f32 "
                    "{%0,%1,%2,%3}, {%4,%5,%6,%7}, {%8,%9}, {%0,%1,%2,%3};"
                    : "+f"(d0), "+f"(d1), "+f"(d2), "+f"(d3)
                    : "r"(a[kk][0]), "r"(a[kk][1]), "r"(a[kk][2]), "r"(a[kk][3]),
                      "r"(b0), "r"(b1));
                asm("mma.sync.aligned.m16n8k8.row.col.f32.tf32.tf32.f32 "
                    "{%0,%1,%2,%3}, {%4,%5,%6,%7}, {%8,%9}, {%0,%1,%2,%3};"
                    : "+f"(e0), "+f"(e1), "+f"(e2), "+f"(e3)
                    : "r"(a[kk][4]), "r"(a[kk][5]), "r"(a[kk][6]), "r"(a[kk][7]),
                      "r"(b0), "r"(b1));
            }
            float* p0 = orow + (size_t)co0      *plane + x;
            float* p1 = orow + (size_t)(co0 + 1)*plane + x;
            __stcs(&p0[0],  lrelu(d0));  __stcs(&p1[0],  lrelu(d1));
            __stcs(&p0[8],  lrelu(d2));  __stcs(&p1[8],  lrelu(d3));
            __stcs(&p0[16], lrelu(e0));  __stcs(&p1[16], lrelu(e1));
            __stcs(&p0[24], lrelu(e2));  __stcs(&p1[24], lrelu(e3));
        }
    }
}

// ---------------------------------------------------------------------------
// Launch
// ---------------------------------------------------------------------------
extern "C" void kernel_launch(void* const* d_in, const int* in_sizes, int n_in,
                              void* d_out, int out_size) {
    (void)in_sizes; (void)n_in; (void)out_size;
    const float* hrms = (const float*)d_in[0];
    const float* msi  = (const float*)d_in[1];
    const float* hsi  = (const float*)d_in[2];
    const float* Wv   = (const float*)d_in[3];
    const float* bv   = (const float*)d_in[4];
    const float* Wq   = (const float*)d_in[5];
    const float* bq   = (const float*)d_in[6];
    const float* Wk   = (const float*)d_in[7];
    const float* bk   = (const float*)d_in[8];
    const float* Wr   = (const float*)d_in[9];
    const float* br   = (const float*)d_in[10];
    float* out = (float*)d_out;

    cudaFuncSetAttribute(final_mma_kernel,
                         cudaFuncAttributeMaxDynamicSharedMemorySize, FINAL_SMEM);

    conv_v_kernel<<<dim3(16, 16, NB), 256>>>(hrms, Wv, bv);
    conv_q_kernel<<<64, 256>>>(msi, Wq, bq);
    qnorm_kernel<<<NB, 256>>>();
    im2col_k_kernel<<<dim3(KK9, NB), 256>>>(hsi);
    wrt_kernel<<<576, 256>>>(Wr);
    gemm_k_kernel<<<dim3(8, 2, NB*SPL), 256>>>(Wk);
    reduce_k_kernel<<<256, 256>>>(bk);
    att2_kernel<<<NB*CMS, 1024>>>();
    weff2_kernel<<<NB*CMS*9, 128>>>();
    final_mma_kernel<<<dim3(HH/2, NB), 256, FINAL_SMEM>>>(br, out);
}

// round 17
// speedup vs baseline: 2.0191x; 1.0461x over previous
#include <cuda_runtime.h>
#include <math.h>
#include <cstdint>

// ---------------------------------------------------------------------------
// Problem constants
// ---------------------------------------------------------------------------
#define NB   2
#define CMS  8
#define CHS  128
#define HH   512
#define HS   128
#define QS   32
#define KK9  (CHS*9)        // 1152 : conv_k im2col K
#define NPX  (QS*QS)        // 1024
#define SPL  8
#define KSP  (KK9/SPL)      // 144

typedef unsigned long long ull;

// ---------------------------------------------------------------------------
// Scratch
// ---------------------------------------------------------------------------
__device__ float g_v[NB*CMS*HH*HH];            // 16 MB
__device__ float g_q[NB*CMS*NPX];
__device__ float g_k[NB*CHS*NPX];
__device__ float g_weff[NB*CMS*9*CHS];         // [n][k=i*9+tap][co]
__device__ float g_kim[NB*KK9*NPX];
__device__ float g_kpart[SPL*NB*CHS*NPX];
__device__ float g_wrt[9*CHS*CHS];             // WrT[tap][c][co]

__device__ __forceinline__ float lrelu(float x) { return x >= 0.f ? x : 0.01f * x; }

#define FMA_F32X2(d, a, b, c) \
    asm("fma.rn.f32x2 %0, %1, %2, %3;" : "=l"(d) : "l"(a), "l"(b), "l"(c))
#define PACK2(out, lo, hi) \
    asm("mov.b64 %0, {%1, %2};" : "=l"(out) : "r"(lo), "r"(hi))
#define UNPACK2(lo, hi, in) \
    asm("mov.b64 {%0, %1}, %2;" : "=r"(lo), "=r"(hi) : "l"(in))
#define CVT_TF32(out, in) \
    asm("cvt.rna.tf32.f32 %0, %1;" : "=r"(out) : "f"(in))

// ===========================================================================
// STAGE 1: im2col + conv_v + conv_q + wrt  (independent input-only bodies)
// ===========================================================================
__device__ void body_conv_v(int b, const float* __restrict__ x,
                            const float* __restrict__ Wv,
                            const float* __restrict__ bv,
                            float* sbuf) {
    float* s_in = sbuf;                   // 8*34*36 = 9792
    float* s_w  = sbuf + 9792;            // 8*9*8 = 576 (16B-aligned: 9792*4%16==0)
    int bx = (b & 15) * 32, by = ((b >> 4) & 15) * 32, n = b >> 8;
    int tid = threadIdx.x;

    for (int e = tid; e < 8*8*9; e += 256) {
        int co = e / 72, rem = e % 72;
        s_w[rem*8 + co] = Wv[e];
    }
    for (int e = tid; e < 8*34*34; e += 256) {
        int cin = e / 1156, rem = e % 1156, r = rem / 34, c = rem % 34;
        int gh = by - 1 + r, gw = bx - 1 + c;
        float v = 0.f;
        if ((unsigned)gh < (unsigned)HH && (unsigned)gw < (unsigned)HH)
            v = x[((n*CMS + cin)*HH + gh)*HH + gw];
        s_in[(cin*34 + r)*36 + c] = v;
    }
    __syncthreads();

    int lx = tid & 31, ly0 = (tid >> 5) * 4;
    ull accp[4][4];
    #pragma unroll
    for (int j = 0; j < 4; j++) {
        ull bj; PACK2(bj, __float_as_uint(bv[2*j]), __float_as_uint(bv[2*j+1]));
        #pragma unroll
        for (int p = 0; p < 4; p++) accp[j][p] = bj;
    }
    #pragma unroll
    for (int cin = 0; cin < 8; cin++) {
        ull vv[6][3];
        #pragma unroll
        for (int rr = 0; rr < 6; rr++)
            #pragma unroll
            for (int dx = 0; dx < 3; dx++) {
                unsigned u = __float_as_uint(s_in[(cin*34 + ly0 + rr)*36 + lx + dx]);
                PACK2(vv[rr][dx], u, u);
            }
        #pragma unroll
        for (int tap = 0; tap < 9; tap++) {
            int dy = tap / 3, dx = tap - dy*3;
            const ulonglong2* wp = (const ulonglong2*)&s_w[(cin*9 + tap)*8];
            ulonglong2 wa = wp[0], wb = wp[1];
            ull wj[4] = {wa.x, wa.y, wb.x, wb.y};
            #pragma unroll
            for (int p = 0; p < 4; p++)
                #pragma unroll
                for (int j = 0; j < 4; j++)
                    FMA_F32X2(accp[j][p], wj[j], vv[p + dy][dx], accp[j][p]);
        }
    }
    #pragma unroll
    for (int j = 0; j < 4; j++)
        #pragma unroll
        for (int p = 0; p < 4; p++) {
            unsigned lo, hi; UNPACK2(lo, hi, accp[j][p]);
            int row = by + ly0 + p;
            g_v[((n*CMS + 2*j    )*HH + row)*HH + bx + lx] = lrelu(__uint_as_float(lo));
            g_v[((n*CMS + 2*j + 1)*HH + row)*HH + bx + lx] = lrelu(__uint_as_float(hi));
        }
}

__device__ void body_conv_q(int b, const float* __restrict__ msi,
                            const float* __restrict__ Wq,
                            const float* __restrict__ bq,
                            float* s_wq) {
    int n = b >> 5, i = (b >> 2) & 7, qy = b & 3;
    int tid = threadIdx.x;
    int ox = tid >> 3, ci = tid & 7;

    if (tid < 72) s_wq[tid] = Wq[i*72 + tid];
    __syncthreads();

    float bias = bq[i];
    for (int r = 0; r < 8; r++) {
        int oy = qy*8 + r;
        float acc = 0.f;
        #pragma unroll
        for (int dy = 0; dy < 3; dy++) {
            int row = oy*16 + dy - 1;
            if ((unsigned)row >= (unsigned)HH) continue;
            #pragma unroll
            for (int dx = 0; dx < 3; dx++) {
                int col = ox*16 + dx - 1;
                if ((unsigned)col >= (unsigned)HH) continue;
                acc = fmaf(s_wq[ci*9 + dy*3 + dx],
                           msi[((n*CMS + ci)*HH + row)*HH + col], acc);
            }
        }
        acc += __shfl_xor_sync(0xffffffffu, acc, 1);
        acc += __shfl_xor_sync(0xffffffffu, acc, 2);
        acc += __shfl_xor_sync(0xffffffffu, acc, 4);
        if (ci == 0)
            g_q[((n*CMS + i)*QS + oy)*QS + ox] = lrelu(acc + bias);
    }
}

__device__ void body_im2col(int b, const float* __restrict__ hsi) {
    int k = b % KK9, n = b / KK9;
    int ci = k / 9, tap = k % 9;
    int dy = tap / 3, dx = tap % 3;
    const float* src = hsi + (n*CHS + ci)*HS*HS;
    float* dst = g_kim + (n*KK9 + k)*NPX;
    for (int px = threadIdx.x; px < NPX; px += 256) {
        int oy = px >> 5, ox = px & 31;
        int row = 4*oy + dy - 1, col = 4*ox + dx - 1;
        float v = 0.f;
        if ((unsigned)row < (unsigned)HS && (unsigned)col < (unsigned)HS)
            v = src[row*HS + col];
        dst[px] = v;
    }
}

__device__ void body_wrt(int b, const float* __restrict__ Wr) {
    int e = b * 256 + threadIdx.x;
    if (e >= 9*CHS*CHS) return;
    int co = e / (CHS*9), rem = e % (CHS*9), c = rem / 9, tap = rem % 9;
    g_wrt[(tap*CHS + c)*CHS + co] = Wr[e];
}

__global__ void __launch_bounds__(256) stage1_kernel(const float* __restrict__ hrms,
                                                     const float* __restrict__ msi,
                                                     const float* __restrict__ hsi,
                                                     const float* __restrict__ Wv,
                                                     const float* __restrict__ bv,
                                                     const float* __restrict__ Wq,
                                                     const float* __restrict__ bq,
                                                     const float* __restrict__ Wr) {
    __shared__ __align__(16) float sbuf[10368];
    int b = blockIdx.x;
    if (b < NB*KK9)                body_im2col(b, hsi);                       // 2304
    else if (b < NB*KK9 + 512)     body_conv_v(b - NB*KK9, hrms, Wv, bv, sbuf);
    else if (b < NB*KK9 + 512+64)  body_conv_q(b - NB*KK9 - 512, msi, Wq, bq, sbuf);
    else                           body_wrt(b - NB*KK9 - 576, Wr);            // 576
}

// ---------------------------------------------------------------------------
// K4b: split-K GEMM for conv_k (f32x2)
// ---------------------------------------------------------------------------
__global__ void __launch_bounds__(256) gemm_k_kernel(const float* __restrict__ Wk) {
    __shared__ __align__(16) float s_w[16*68];
    __shared__ __align__(16) float s_im[16*128];
    int px0 = blockIdx.x * 128;
    int co0 = blockIdx.y * 64;
    int z = blockIdx.z;
    int n = z >> 3, s = z & 7;
    int k0 = s * KSP;
    int tid = threadIdx.x;
    int c8 = tid >> 5, pxq = tid & 31;

    ull acc[4][4];
    #pragma unroll
    for (int j = 0; j < 4; j++)
        #pragma unroll
        for (int p = 0; p < 4; p++) acc[j][p] = 0ull;

    for (int cc = 0; cc < KSP/16; cc++) {
        int kbase = k0 + cc*16;
        #pragma unroll
        for (int e = tid; e < 1024; e += 256) {
            int co = e >> 4, kk = e & 15;
            s_w[kk*68 + co] = Wk[(co0 + co)*KK9 + kbase + kk];
        }
        #pragma unroll
        for (int e = tid; e < 2048; e += 256) {
            int kk = e >> 7, p = e & 127;
            s_im[kk*128 + p] = g_kim[(n*KK9 + kbase + kk)*NPX + px0 + p];
        }
        __syncthreads();
        #pragma unroll
        for (int kk = 0; kk < 16; kk++) {
            const ulonglong2* wp = (const ulonglong2*)&s_w[kk*68 + c8*8];
            ulonglong2 wa = wp[0], wb = wp[1];
            ull wj[4] = {wa.x, wa.y, wb.x, wb.y};
            float4 im = *(const float4*)&s_im[kk*128 + pxq*4];
            float imv[4] = {im.x, im.y, im.z, im.w};
            #pragma unroll
            for (int p = 0; p < 4; p++) {
                unsigned u = __float_as_uint(imv[p]);
                ull vv; PACK2(vv, u, u);
                #pragma unroll
                for (int j = 0; j < 4; j++)
                    FMA_F32X2(acc[j][p], wj[j], vv, acc[j][p]);
            }
        }
        __syncthreads();
    }

    int pbase = (s*NB + n)*CHS;
    #pragma unroll
    for (int j = 0; j < 4; j++) {
        int co = co0 + c8*8 + 2*j;
        #pragma unroll
        for (int p = 0; p < 4; p++) {
            unsigned lo, hi; UNPACK2(lo, hi, acc[j][p]);
            int px = px0 + pxq*4 + p;
            g_kpart[(pbase + co    )*NPX + px] = __uint_as_float(lo);
            g_kpart[(pbase + co + 1)*NPX + px] = __uint_as_float(hi);
        }
    }
}

// ---------------------------------------------------------------------------
// K4c: reduce split-K partials + bias + lrelu -> g_k
// ---------------------------------------------------------------------------
__global__ void __launch_bounds__(256) reduce_k_kernel(const float* __restrict__ bk) {
    int idx4 = blockIdx.x * 256 + threadIdx.x;
    int idx = idx4 * 4;
    int co = (idx >> 10) & 127;
    float4 sum = make_float4(0.f, 0.f, 0.f, 0.f);
    #pragma unroll
    for (int s = 0; s < SPL; s++) {
        float4 v = ((const float4*)g_kpart)[s*65536 + idx4];
        sum.x += v.x; sum.y += v.y; sum.z += v.z; sum.w += v.w;
    }
    float b = bk[co];
    float4 o;
    o.x = lrelu(sum.x + b); o.y = lrelu(sum.y + b);
    o.z = lrelu(sum.z + b); o.w = lrelu(sum.w + b);
    ((float4*)g_k)[idx4] = o;
}

// ===========================================================================
// STAGE 4: attweff3 — qnorm + att dot + softmax + weff.  16 blocks x 1024.
// ===========================================================================
__global__ void __launch_bounds__(1024) attweff3_kernel() {
    __shared__ __align__(16) float s_q[NPX];
    __shared__ float s_red[128];
    __shared__ float s_norm[32];
    __shared__ float s_att[128];
    __shared__ float s_sc[3];

    int b = blockIdx.x, n = b >> 3;
    int tid = threadIdx.x;
    int lane = tid & 31, w = tid >> 5;
    int c = tid >> 3, t8 = tid & 7;

    s_q[tid] = g_q[b*NPX + tid];

    // --- k0max: warp w sums band (w&7), chunk (w>>3) of 256 elems ---
    {
        int band = w & 7, chunk = w >> 3;
        const float* qp = g_q + (n*CMS + band)*NPX + chunk*256;
        float s = 0.f;
        #pragma unroll
        for (int j = 0; j < 8; j++) { float v = qp[lane + j*32]; s += v*v; }
        #pragma unroll
        for (int o = 16; o; o >>= 1) s += __shfl_xor_sync(0xffffffffu, s, o);
        if (lane == 0) s_norm[w] = s;
    }
    __syncthreads();
    if (tid == 0) {
        float m = 0.f;
        #pragma unroll
        for (int i = 0; i < 8; i++) {
            float nr = sqrtf(s_norm[i] + s_norm[8+i] + s_norm[16+i] + s_norm[24+i]);
            m = fmaxf(m, nr);
        }
        s_sc[2] = 10.0f / m;
    }
    __syncthreads();

    // --- dot <q, k[c]>: 8 lanes per channel, coalesced float4 ---
    const float4* kp = (const float4*)(g_k + (n*CHS + c)*NPX);
    const float4* qp = (const float4*)s_q;
    float acc = 0.f;
    #pragma unroll 8
    for (int j = 0; j < 32; j++) {
        int i4 = t8 + j*8;
        float4 kv = kp[i4], qv = qp[i4];
        acc += kv.x*qv.x + kv.y*qv.y + kv.z*qv.z + kv.w*qv.w;
    }
    acc += __shfl_xor_sync(0xffffffffu, acc, 1);
    acc += __shfl_xor_sync(0xffffffffu, acc, 2);
    acc += __shfl_xor_sync(0xffffffffu, acc, 4);
    if (t8 == 0) s_red[c] = acc;
    __syncthreads();

    // --- softmax over 128 channels ---
    float s = 0.f;
    if (tid < 128) { s = s_red[tid] * s_sc[2]; s_red[tid] = s; }
    __syncthreads();
    for (int off = 64; off; off >>= 1) {
        if (tid < off) s_red[tid] = fmaxf(s_red[tid], s_red[tid + off]);
        __syncthreads();
    }
    if (tid == 0) s_sc[0] = s_red[0];
    __syncthreads();
    float e = 0.f;
    if (tid < 128) { e = expf(s - s_sc[0]); s_red[tid] = e; }
    __syncthreads();
    for (int off = 64; off; off >>= 1) {
        if (tid < off) s_red[tid] += s_red[tid + off];
        __syncthreads();
    }
    if (tid == 0) s_sc[1] = s_red[0];
    __syncthreads();
    if (tid < 128) s_att[tid] = e / s_sc[1];
    __syncthreads();

    // --- weff: grp = tid>>7 handles taps grp, grp+8; co = tid&127 ---
    int grp = tid >> 7, co = tid & 127;
    for (int tap = grp; tap < 9; tap += 8) {
        const float* wp = g_wrt + tap*CHS*CHS + co;
        float a9 = 0.f;
        #pragma unroll 8
        for (int cc = 0; cc < 128; cc++)
            a9 = fmaf(s_att[cc], wp[cc*CHS], a9);
        g_weff[(b*9 + tap)*CHS + co] = a9 * (1.0f/6.0f);
    }
}

// ---------------------------------------------------------------------------
// K7: final conv via mma.sync tf32 (unchanged measured-good 184.4us version)
// ---------------------------------------------------------------------------
#define HALO_STRIDE 516
#define HALO_ROWS   4
#define HALO_FLOATS (8*HALO_ROWS*HALO_STRIDE)   // 16512
#define BSTR 136
#define B_FLOATS (72*BSTR)                      // 9792
#define FINAL_SMEM ((HALO_FLOATS + B_FLOATS + 128) * 4)   // 105728 B

__global__ void __launch_bounds__(256, 2) final_mma_kernel(const float* __restrict__ br,
                                                           float* __restrict__ out) {
    extern __shared__ float sm[];
    float*    s_halo = sm;                                   // 16512 floats
    uint32_t* s_B    = (uint32_t*)(sm + HALO_FLOATS);        // 9792 (tf32)
    float*    s_br   = sm + HALO_FLOATS + B_FLOATS;          // 128

    int y0 = blockIdx.x * 2;
    int n = blockIdx.y;
    int tid = threadIdx.x;
    int lane = tid & 31, w = tid >> 5;
    int q = lane & 3, r = lane >> 2;

    const float* wsrc = g_weff + n*72*128;
    for (int e = tid; e < 72*128; e += 256) {
        int k = e >> 7, co = e & 127;
        uint32_t t; CVT_TF32(t, wsrc[k*128 + co]);
        s_B[k*BSTR + co] = t;
    }
    if (tid < 128) s_br[tid] = br[tid];

    for (int e = tid; e < 8*HALO_ROWS*514; e += 256) {
        int cin = e / (HALO_ROWS*514), rem = e % (HALO_ROWS*514);
        int rr = rem / 514, cc = rem % 514;
        int gh = y0 - 1 + rr, gw = cc - 1;
        float v = 0.f;
        if ((unsigned)gh < (unsigned)HH && (unsigned)gw < (unsigned)HH)
            v = g_v[((n*CMS + cin)*HH + gh)*HH + gw];
        s_halo[(cin*HALO_ROWS + rr)*HALO_STRIDE + cc] = v;
    }
    __syncthreads();

    int off0[9], off1[9];
    #pragma unroll
    for (int kk = 0; kk < 9; kk++) {
        int k = kk*8 + q;
        int cin = k / 9, tap = k % 9;
        off0[kk] = (cin*HALO_ROWS + tap/3)*HALO_STRIDE + (tap%3);
        k += 4; cin = k / 9; tap = k % 9;
        off1[kk] = (cin*HALO_ROWS + tap/3)*HALO_STRIDE + (tap%3);
    }

    const size_t plane = (size_t)HH * HH;
    float* obase = out + (size_t)(n*CHS) * plane;

    #pragma unroll
    for (int i = 0; i < 4; i++) {
        int yr = i >> 1;
        int yofs = yr * HALO_STRIDE;
        int x = w*64 + (i & 1)*32 + r;
        float* orow = obase + (size_t)(y0 + yr) * HH;

        uint32_t a[9][8];
        #pragma unroll
        for (int kk = 0; kk < 9; kk++) {
            CVT_TF32(a[kk][0], s_halo[off0[kk] + yofs + x]);
            CVT_TF32(a[kk][1], s_halo[off0[kk] + yofs + x + 8]);
            CVT_TF32(a[kk][2], s_halo[off1[kk] + yofs + x]);
            CVT_TF32(a[kk][3], s_halo[off1[kk] + yofs + x + 8]);
            CVT_TF32(a[kk][4], s_halo[off0[kk] + yofs + x + 16]);
            CVT_TF32(a[kk][5], s_halo[off0[kk] + yofs + x + 24]);
            CVT_TF32(a[kk][6], s_halo[off1[kk] + yofs + x + 16]);
            CVT_TF32(a[kk][7], s_halo[off1[kk] + yofs + x + 24]);
        }

        for (int nt = 0; nt < 16; nt++) {
            int n0  = nt * 8;
            int co0 = n0 + 2*q;
            float2 bi = *(const float2*)&s_br[co0];
            float d0 = bi.x, d1 = bi.y, d2 = bi.x, d3 = bi.y;
            float e0 = bi.x, e1 = bi.y, e2 = bi.x, e3 = bi.y;
            const uint32_t* bp = &s_B[q*BSTR + n0 + r];
            #pragma unroll
            for (int kk = 0; kk < 9; kk++) {
                uint32_t b0 = bp[(kk*8    )*BSTR];
                uint32_t b1 = bp[(kk*8 + 4)*BSTR];
                asm("mma.sync.aligned.m16n8k8.row.col.f32.tf32.tf32.f32 "
                    "{%0,%1,%2,%3}, {%4,%5,%6,%7}, {%8,%9}, {%0,%1,%2,%3};"
                    : "+f"(d0), "+f"(d1), "+f"(d2), "+f"(d3)
                    : "r"(a[kk][0]), "r"(a[kk][1]), "r"(a[kk][2]), "r"(a[kk][3]),
                      "r"(b0), "r"(b1));
                asm("mma.sync.aligned.m16n8k8.row.col.f32.tf32.tf32.f32 "
                    "{%0,%1,%2,%3}, {%4,%5,%6,%7}, {%8,%9}, {%0,%1,%2,%3};"
                    : "+f"(e0), "+f"(e1), "+f"(e2), "+f"(e3)
                    : "r"(a[kk][4]), "r"(a[kk][5]), "r"(a[kk][6]), "r"(a[kk][7]),
                      "r"(b0), "r"(b1));
            }
            float* p0 = orow + (size_t)co0      *plane + x;
            float* p1 = orow + (size_t)(co0 + 1)*plane + x;
            __stcs(&p0[0],  lrelu(d0));  __stcs(&p1[0],  lrelu(d1));
            __stcs(&p0[8],  lrelu(d2));  __stcs(&p1[8],  lrelu(d3));
            __stcs(&p0[16], lrelu(e0));  __stcs(&p1[16], lrelu(e1));
            __stcs(&p0[24], lrelu(e2));  __stcs(&p1[24], lrelu(e3));
        }
    }
}

// ---------------------------------------------------------------------------
// Launch
// ---------------------------------------------------------------------------
extern "C" void kernel_launch(void* const* d_in, const int* in_sizes, int n_in,
                              void* d_out, int out_size) {
    (void)in_sizes; (void)n_in; (void)out_size;
    const float* hrms = (const float*)d_in[0];
    const float* msi  = (const float*)d_in[1];
    const float* hsi  = (const float*)d_in[2];
    const float* Wv   = (const float*)d_in[3];
    const float* bv   = (const float*)d_in[4];
    const float* Wq   = (const float*)d_in[5];
    const float* bq   = (const float*)d_in[6];
    const float* Wk   = (const float*)d_in[7];
    const float* bk   = (const float*)d_in[8];
    const float* Wr   = (const float*)d_in[9];
    const float* br   = (const float*)d_in[10];
    float* out = (float*)d_out;

    cudaFuncSetAttribute(final_mma_kernel,
                         cudaFuncAttributeMaxDynamicSharedMemorySize, FINAL_SMEM);

    stage1_kernel<<<NB*KK9 + 512 + 64 + 576, 256>>>(hrms, msi, hsi, Wv, bv, Wq, bq, Wr);
    gemm_k_kernel<<<dim3(8, 2, NB*SPL), 256>>>(Wk);
    reduce_k_kernel<<<256, 256>>>(bk);
    attweff3_kernel<<<NB*CMS, 1024>>>();
    final_mma_kernel<<<dim3(HH/2, NB), 256, FINAL_SMEM>>>(br, out);
}